// round 1
// baseline (speedup 1.0000x reference)
#include <cuda_runtime.h>
#include <cstdint>

// Problem constants
#define SEQ   2048
#define BATCH 4
#define DIM   256
#define NHEAD 8
#define HDIM  32
#define M_TOT 8192          // BATCH*SEQ
#define QK_SCALE 0.17677669529663687f  // 1/sqrt(32)

// Scratch (device globals: allocation-free rule)
__device__ float g_xn [M_TOT*DIM];
__device__ float g_qkv[M_TOT*3*DIM];
__device__ float g_att[M_TOT*DIM];
__device__ float g_y  [M_TOT*DIM];
__device__ float g_z  [M_TOT*DIM];
__device__ float g_r  [M_TOT*DIM];

// ---------------------------------------------------------------------------
// LayerNorm: one block per row, 256 threads (one per column)
// ---------------------------------------------------------------------------
__global__ void ln_kernel(const float* __restrict__ x,
                          const float* __restrict__ gamma,
                          const float* __restrict__ beta,
                          float* __restrict__ out)
{
    const int row = blockIdx.x;
    const int tid = threadIdx.x;
    const float v = x[(size_t)row*DIM + tid];
    float s = v, s2 = v*v;
    #pragma unroll
    for (int o = 16; o; o >>= 1) {
        s  += __shfl_xor_sync(0xffffffffu, s,  o);
        s2 += __shfl_xor_sync(0xffffffffu, s2, o);
    }
    __shared__ float ps[8], ps2[8];
    if ((tid & 31) == 0) { ps[tid>>5] = s; ps2[tid>>5] = s2; }
    __syncthreads();
    float tot = 0.f, tot2 = 0.f;
    #pragma unroll
    for (int i = 0; i < 8; i++) { tot += ps[i]; tot2 += ps2[i]; }
    const float mu   = tot * (1.0f/DIM);
    const float var  = tot2 * (1.0f/DIM) - mu*mu;
    const float rstd = rsqrtf(var + 1e-5f);
    out[(size_t)row*DIM + tid] = (v - mu) * rstd * gamma[tid] + beta[tid];
}

// ---------------------------------------------------------------------------
// Generic NT SGEMM, 128x128x16 tile, 256 threads, 8x8 micro-tile.
// C[m,n] = sum_k A[m,k] * B[n,k] (+ optional second source) + epilogue.
// K is fixed at 256 per source. Modes:
//   0 QKV : C = A1@B1^T + bias           -> g_qkv (ldc=768)
//   1 FC  : C = relu(A1@B1^T + bias)     -> g_y
//   2 Z   : C = sigmoid(A1@B1^T + A2@B2^T + bias) -> g_z
//   3 R   : C = sigmoid(A1@B1^T + A2@B2^T)        -> g_r
//   4 H   : acc = A1@B1^T + (Rm.*A2)@B2^T ; C = (1-z)*res + z*tanh(acc)
// ---------------------------------------------------------------------------
enum { MODE_QKV = 0, MODE_FC = 1, MODE_Z = 2, MODE_R = 3, MODE_H = 4 };

__global__ void __launch_bounds__(256)
gemm128(const float* __restrict__ A1, const float* __restrict__ B1,
        const float* __restrict__ A2, const float* __restrict__ B2,
        const float* __restrict__ bias,
        const float* __restrict__ Rm,
        const float* __restrict__ Zb,
        const float* __restrict__ Res,
        float* __restrict__ C, int mode)
{
    __shared__ float As[16][128];
    __shared__ float Bs[16][128];
    const int tid = threadIdx.x;
    const int tx = tid & 15, ty = tid >> 4;
    const int m0 = blockIdx.y * 128;
    const int n0 = blockIdx.x * 128;

    float acc[8][8];
    #pragma unroll
    for (int i = 0; i < 8; i++)
        #pragma unroll
        for (int j = 0; j < 8; j++) acc[i][j] = 0.f;

    const int ntiles = (mode >= MODE_Z) ? 32 : 16;
    for (int kt = 0; kt < ntiles; kt++) {
        const int phase = (kt >= 16);
        const float* __restrict__ Ap = phase ? A2 : A1;
        const float* __restrict__ Bp = phase ? B2 : B1;
        const int k0 = (kt - (phase ? 16 : 0)) * 16;

        #pragma unroll
        for (int it = 0; it < 2; it++) {
            const int i  = tid + it * 256;        // 0..511
            const int r  = i >> 2;                // 0..127
            const int kq = (i & 3) << 2;          // 0,4,8,12
            float4 va = *(const float4*)&Ap[(size_t)(m0 + r)*256 + k0 + kq];
            if (mode == MODE_H && phase) {
                const float4 vr = *(const float4*)&Rm[(size_t)(m0 + r)*256 + k0 + kq];
                va.x *= vr.x; va.y *= vr.y; va.z *= vr.z; va.w *= vr.w;
            }
            As[kq  ][r] = va.x; As[kq+1][r] = va.y;
            As[kq+2][r] = va.z; As[kq+3][r] = va.w;
            const float4 vb = *(const float4*)&Bp[(size_t)(n0 + r)*256 + k0 + kq];
            Bs[kq  ][r] = vb.x; Bs[kq+1][r] = vb.y;
            Bs[kq+2][r] = vb.z; Bs[kq+3][r] = vb.w;
        }
        __syncthreads();

        #pragma unroll
        for (int kk = 0; kk < 16; kk++) {
            const float4 a0 = *(const float4*)&As[kk][ty*8];
            const float4 a1 = *(const float4*)&As[kk][ty*8 + 4];
            const float4 b0 = *(const float4*)&Bs[kk][tx*8];
            const float4 b1 = *(const float4*)&Bs[kk][tx*8 + 4];
            const float av[8] = {a0.x,a0.y,a0.z,a0.w,a1.x,a1.y,a1.z,a1.w};
            const float bv[8] = {b0.x,b0.y,b0.z,b0.w,b1.x,b1.y,b1.z,b1.w};
            #pragma unroll
            for (int i = 0; i < 8; i++)
                #pragma unroll
                for (int j = 0; j < 8; j++)
                    acc[i][j] = fmaf(av[i], bv[j], acc[i][j]);
        }
        __syncthreads();
    }

    const int ldc = (mode == MODE_QKV) ? 768 : 256;
    #pragma unroll
    for (int i = 0; i < 8; i++) {
        const int m = m0 + ty*8 + i;
        #pragma unroll
        for (int jj = 0; jj < 2; jj++) {
            float4 o;
            float* op = (float*)&o;
            #pragma unroll
            for (int t = 0; t < 4; t++) {
                const int n = n0 + tx*8 + jj*4 + t;
                float c = acc[i][jj*4 + t];
                if      (mode == MODE_QKV) c += bias[n];
                else if (mode == MODE_FC)  c = fmaxf(c + bias[n], 0.f);
                else if (mode == MODE_Z)   c = 1.f/(1.f + __expf(-(c + bias[n])));
                else if (mode == MODE_R)   c = 1.f/(1.f + __expf(-c));
                else {
                    const float zz = Zb [(size_t)m*256 + n];
                    const float rs = Res[(size_t)m*256 + n];
                    c = (1.f - zz)*rs + zz*tanhf(c);
                }
                op[t] = c;
            }
            *(float4*)&C[(size_t)m*ldc + n0 + tx*8 + jj*4] = o;
        }
    }
}

// ---------------------------------------------------------------------------
// Flash attention (fp32), per-(b,h) CTA, Q tile = 64, K tile = 64, 128 threads.
// qkv layout per row (b*2048+s): head h -> q at col h*96, k at h*96+32, v at h*96+64.
// Output written in the reference's permuted layout:
//   n = b*8+h ;  out[(n%4)*2048 + s][ (n/4)*32 + hd ]
// ---------------------------------------------------------------------------
__global__ void __launch_bounds__(128)
attn_kernel(const float* __restrict__ qkv,
            const int*   __restrict__ adj,
            float* __restrict__ outp)
{
    const int qt = blockIdx.x;           // 0..31
    const int h  = blockIdx.y;           // 0..7
    const int b  = blockIdx.z;           // 0..3
    const int q0 = qt * 64;

    __shared__ float Qs[32][64];         // [kk][q]
    __shared__ float Ks[32][64];         // [kk][k]
    __shared__ float Vs[64][32];         // [k][hd]
    __shared__ float Ss[64][68];         // scores / probs (+pad)

    const int tid = threadIdx.x;

    // Q tile load, transposed: 64 rows x 8 float4
    for (int i = tid; i < 512; i += 128) {
        const int rr = i >> 3, kq = (i & 7) << 2;
        const float4 v = *(const float4*)&qkv[((size_t)(b*SEQ + q0 + rr))*768 + h*96 + kq];
        Qs[kq  ][rr] = v.x; Qs[kq+1][rr] = v.y;
        Qs[kq+2][rr] = v.z; Qs[kq+3][rr] = v.w;
    }

    const int r_sm = tid >> 1;           // row this thread owns for softmax/PV
    const int g    = tid & 1;            // half: cols g*32.., hd g*16..
    const int sr0  = (tid >> 3) << 2;    // score micro-tile: 4 rows
    const int sc0  = (tid & 7)  << 3;    // score micro-tile: 8 cols

    float m_i = -1e30f, l_i = 0.f;
    float acc[16];
    #pragma unroll
    for (int d = 0; d < 16; d++) acc[d] = 0.f;

    for (int kt = 0; kt < 32; kt++) {
        const int k0 = kt * 64;
        __syncthreads();   // previous PV done reading Ss/Vs; Qs ready on iter 0

        // K (transposed) and V tile loads
        for (int i = tid; i < 512; i += 128) {
            const int c = i >> 3, kq = (i & 7) << 2;
            const float4 v = *(const float4*)&qkv[((size_t)(b*SEQ + k0 + c))*768 + h*96 + 32 + kq];
            Ks[kq  ][c] = v.x; Ks[kq+1][c] = v.y;
            Ks[kq+2][c] = v.z; Ks[kq+3][c] = v.w;
        }
        for (int i = tid; i < 512; i += 128) {
            const int j = i >> 3, dq = (i & 7) << 2;
            *(float4*)&Vs[j][dq] =
                *(const float4*)&qkv[((size_t)(b*SEQ + k0 + j))*768 + h*96 + 64 + dq];
        }
        __syncthreads();

        // Scores: 4x8 micro-tile per thread, K-dim 32
        float s[4][8];
        #pragma unroll
        for (int i = 0; i < 4; i++)
            #pragma unroll
            for (int j = 0; j < 8; j++) s[i][j] = 0.f;
        #pragma unroll
        for (int kk = 0; kk < 32; kk++) {
            const float4 a  = *(const float4*)&Qs[kk][sr0];
            const float4 c0 = *(const float4*)&Ks[kk][sc0];
            const float4 c1 = *(const float4*)&Ks[kk][sc0 + 4];
            const float av[4] = {a.x, a.y, a.z, a.w};
            const float bv[8] = {c0.x,c0.y,c0.z,c0.w,c1.x,c1.y,c1.z,c1.w};
            #pragma unroll
            for (int i = 0; i < 4; i++)
                #pragma unroll
                for (int j = 0; j < 8; j++)
                    s[i][j] = fmaf(av[i], bv[j], s[i][j]);
        }
        // mask + scale + stage to smem
        #pragma unroll
        for (int i = 0; i < 4; i++) {
            const size_t arow = ((size_t)b*SEQ + (q0 + sr0 + i))*SEQ + k0 + sc0;
            const int4 ma = *(const int4*)&adj[arow];
            const int4 mb = *(const int4*)&adj[arow + 4];
            float4 o0, o1;
            o0.x = ma.x ? s[i][0]*QK_SCALE : -1e30f;
            o0.y = ma.y ? s[i][1]*QK_SCALE : -1e30f;
            o0.z = ma.z ? s[i][2]*QK_SCALE : -1e30f;
            o0.w = ma.w ? s[i][3]*QK_SCALE : -1e30f;
            o1.x = mb.x ? s[i][4]*QK_SCALE : -1e30f;
            o1.y = mb.y ? s[i][5]*QK_SCALE : -1e30f;
            o1.z = mb.z ? s[i][6]*QK_SCALE : -1e30f;
            o1.w = mb.w ? s[i][7]*QK_SCALE : -1e30f;
            *(float4*)&Ss[sr0 + i][sc0    ] = o0;
            *(float4*)&Ss[sr0 + i][sc0 + 4] = o1;
        }
        __syncthreads();

        // Online softmax: 2 threads per row, 32 cols each
        {
            float* prow = &Ss[r_sm][g*32];
            float mloc = -1e30f;
            #pragma unroll
            for (int j = 0; j < 32; j++) mloc = fmaxf(mloc, prow[j]);
            mloc = fmaxf(mloc, __shfl_xor_sync(0xffffffffu, mloc, 1));
            const float m_new = fmaxf(m_i, mloc);
            const float alpha = __expf(m_i - m_new);
            float lsum = 0.f;
            #pragma unroll
            for (int j = 0; j < 32; j++) {
                const float p = __expf(prow[j] - m_new);
                prow[j] = p;
                lsum += p;
            }
            m_i = m_new;
            l_i = l_i * alpha + lsum;
            #pragma unroll
            for (int d = 0; d < 16; d++) acc[d] *= alpha;
        }
        __syncthreads();

        // PV: acc[d] += sum_j P[r][j] * V[j][g*16+d]
        for (int j = 0; j < 64; j += 4) {
            const float4 p4 = *(const float4*)&Ss[r_sm][j];
            const float pv[4] = {p4.x, p4.y, p4.z, p4.w};
            #pragma unroll
            for (int t = 0; t < 4; t++) {
                const float p = pv[t];
                const float4 v0 = *(const float4*)&Vs[j+t][g*16     ];
                const float4 v1 = *(const float4*)&Vs[j+t][g*16 +  4];
                const float4 v2 = *(const float4*)&Vs[j+t][g*16 +  8];
                const float4 v3 = *(const float4*)&Vs[j+t][g*16 + 12];
                acc[0]  = fmaf(p, v0.x, acc[0]);  acc[1]  = fmaf(p, v0.y, acc[1]);
                acc[2]  = fmaf(p, v0.z, acc[2]);  acc[3]  = fmaf(p, v0.w, acc[3]);
                acc[4]  = fmaf(p, v1.x, acc[4]);  acc[5]  = fmaf(p, v1.y, acc[5]);
                acc[6]  = fmaf(p, v1.z, acc[6]);  acc[7]  = fmaf(p, v1.w, acc[7]);
                acc[8]  = fmaf(p, v2.x, acc[8]);  acc[9]  = fmaf(p, v2.y, acc[9]);
                acc[10] = fmaf(p, v2.z, acc[10]); acc[11] = fmaf(p, v2.w, acc[11]);
                acc[12] = fmaf(p, v3.x, acc[12]); acc[13] = fmaf(p, v3.y, acc[13]);
                acc[14] = fmaf(p, v3.z, acc[14]); acc[15] = fmaf(p, v3.w, acc[15]);
            }
        }
    }

    // finalize row sum over the two half-threads, normalize, write permuted
    l_i += __shfl_xor_sync(0xffffffffu, l_i, 1);
    const float inv = 1.f / l_i;
    const int n  = b*NHEAD + h;
    const int bo = n & 3;
    const int hp = n >> 2;
    float* dst = &outp[((size_t)(bo*SEQ + q0 + r_sm))*DIM + hp*HDIM + g*16];
    #pragma unroll
    for (int d = 0; d < 16; d += 4) {
        const float4 o = make_float4(acc[d]*inv, acc[d+1]*inv, acc[d+2]*inv, acc[d+3]*inv);
        *(float4*)&dst[d] = o;
    }
}

// ---------------------------------------------------------------------------
extern "C" void kernel_launch(void* const* d_in, const int* in_sizes, int n_in,
                              void* d_out, int out_size)
{
    const float* x     = (const float*)d_in[0];
    const int*   adj   = (const int*)  d_in[1];
    const float* w_qkv = (const float*)d_in[2];
    const float* b_qkv = (const float*)d_in[3];
    const float* ln_g  = (const float*)d_in[4];
    const float* ln_b  = (const float*)d_in[5];
    const float* w_fc  = (const float*)d_in[6];
    const float* b_fc  = (const float*)d_in[7];
    const float* w_z   = (const float*)d_in[8];
    const float* b_z   = (const float*)d_in[9];
    const float* u_z   = (const float*)d_in[10];
    const float* w_r   = (const float*)d_in[11];
    const float* u_r   = (const float*)d_in[12];
    const float* w_g   = (const float*)d_in[13];
    const float* u_g   = (const float*)d_in[14];
    float* out = (float*)d_out;

    float *xn, *qkv, *att, *y, *z, *r;
    cudaGetSymbolAddress((void**)&xn,  g_xn);
    cudaGetSymbolAddress((void**)&qkv, g_qkv);
    cudaGetSymbolAddress((void**)&att, g_att);
    cudaGetSymbolAddress((void**)&y,   g_y);
    cudaGetSymbolAddress((void**)&z,   g_z);
    cudaGetSymbolAddress((void**)&r,   g_r);

    // 1. LayerNorm
    ln_kernel<<<M_TOT, 256>>>(x, ln_g, ln_b, xn);
    // 2. QKV projection: [8192,256] x [768,256]^T
    gemm128<<<dim3(6, 64), 256>>>(xn, w_qkv, nullptr, nullptr, b_qkv,
                                  nullptr, nullptr, nullptr, qkv, MODE_QKV);
    // 3. Masked flash attention (writes permuted layout)
    attn_kernel<<<dim3(SEQ/64, NHEAD, BATCH), 128>>>(qkv, adj, att);
    // 4. FC + ReLU
    gemm128<<<dim3(2, 64), 256>>>(att, w_fc, nullptr, nullptr, b_fc,
                                  nullptr, nullptr, nullptr, y, MODE_FC);
    // 5. z = sigmoid(y@w_z^T + b_z + x@u_z^T)
    gemm128<<<dim3(2, 64), 256>>>(y, w_z, x, u_z, b_z,
                                  nullptr, nullptr, nullptr, z, MODE_Z);
    // 6. r = sigmoid(y@w_r^T + x@u_r^T)
    gemm128<<<dim3(2, 64), 256>>>(y, w_r, x, u_r, nullptr,
                                  nullptr, nullptr, nullptr, r, MODE_R);
    // 7. h_hat = tanh(y@w_g^T + (r.*x)@u_g^T); out = (1-z)*x + z*h_hat
    gemm128<<<dim3(2, 64), 256>>>(y, w_g, x, u_g, nullptr,
                                  r, z, x, out, MODE_H);
}

// round 2
// speedup vs baseline: 2.1276x; 2.1276x over previous
#include <cuda_runtime.h>
#include <cuda_bf16.h>
#include <cstdint>

// Problem constants
#define SEQ   2048
#define BATCH 4
#define DIM   256
#define NHEAD 8
#define HDIM  32
#define M_TOT 8192          // BATCH*SEQ
#define QK_SCALE 0.17677669529663687f  // 1/sqrt(32)

// Scratch (device globals: allocation-free rule)
__device__ float g_xn [M_TOT*DIM];
__device__ float g_att[M_TOT*DIM];
__device__ float g_y  [M_TOT*DIM];
__device__ float g_z  [M_TOT*DIM];
__device__ float g_r  [M_TOT*DIM];
__device__ __nv_bfloat16 g_q[M_TOT*HDIM*NHEAD];   // [B*H, S, 32]
__device__ __nv_bfloat16 g_k[M_TOT*HDIM*NHEAD];
__device__ __nv_bfloat16 g_v[M_TOT*HDIM*NHEAD];
__device__ uint32_t g_mask[BATCH*SEQ*(SEQ/32)];   // 2MB bit mask

// ---------------------------------------------------------------------------
// adj -> bitmask (ballot pack). grid 65536 x 256.
// ---------------------------------------------------------------------------
__global__ void pack_adj(const int* __restrict__ adj, uint32_t* __restrict__ mask)
{
    const int idx = blockIdx.x * 256 + threadIdx.x;
    const int v = adj[idx];
    const uint32_t bal = __ballot_sync(0xffffffffu, v != 0);
    if ((threadIdx.x & 31) == 0) mask[idx >> 5] = bal;
}

// ---------------------------------------------------------------------------
// LayerNorm: one block per row, 256 threads (one per column)
// ---------------------------------------------------------------------------
__global__ void ln_kernel(const float* __restrict__ x,
                          const float* __restrict__ gamma,
                          const float* __restrict__ beta,
                          float* __restrict__ out)
{
    const int row = blockIdx.x;
    const int tid = threadIdx.x;
    const float v = x[(size_t)row*DIM + tid];
    float s = v, s2 = v*v;
    #pragma unroll
    for (int o = 16; o; o >>= 1) {
        s  += __shfl_xor_sync(0xffffffffu, s,  o);
        s2 += __shfl_xor_sync(0xffffffffu, s2, o);
    }
    __shared__ float ps[8], ps2[8];
    if ((tid & 31) == 0) { ps[tid>>5] = s; ps2[tid>>5] = s2; }
    __syncthreads();
    float tot = 0.f, tot2 = 0.f;
    #pragma unroll
    for (int i = 0; i < 8; i++) { tot += ps[i]; tot2 += ps2[i]; }
    const float mu   = tot * (1.0f/DIM);
    const float var  = tot2 * (1.0f/DIM) - mu*mu;
    const float rstd = rsqrtf(var + 1e-5f);
    out[(size_t)row*DIM + tid] = (v - mu) * rstd * gamma[tid] + beta[tid];
}

// ---------------------------------------------------------------------------
// Generic NT SGEMM, 128x128x16 tile, 256 threads, 8x8 micro-tile.
// Modes:
//   0 QKV : C = A1@B1^T + bias  -> bf16 scatter into g_q (x QK_SCALE), g_k, g_v
//   1 FC  : C = relu(A1@B1^T + bias)     -> g_y
//   2 Z   : C = sigmoid(A1@B1^T + A2@B2^T + bias) -> g_z
//   3 R   : C = sigmoid(A1@B1^T + A2@B2^T)        -> g_r
//   4 H   : acc = A1@B1^T + (Rm.*A2)@B2^T ; C = (1-z)*res + z*tanh(acc)
// ---------------------------------------------------------------------------
enum { MODE_QKV = 0, MODE_FC = 1, MODE_Z = 2, MODE_R = 3, MODE_H = 4 };

__global__ void __launch_bounds__(256)
gemm128(const float* __restrict__ A1, const float* __restrict__ B1,
        const float* __restrict__ A2, const float* __restrict__ B2,
        const float* __restrict__ bias,
        const float* __restrict__ Rm,
        const float* __restrict__ Zb,
        const float* __restrict__ Res,
        float* __restrict__ C,
        __nv_bfloat16* __restrict__ qb,
        __nv_bfloat16* __restrict__ kb,
        __nv_bfloat16* __restrict__ vb,
        int mode)
{
    __shared__ float As[16][128];
    __shared__ float Bs[16][128];
    const int tid = threadIdx.x;
    const int tx = tid & 15, ty = tid >> 4;
    const int m0 = blockIdx.y * 128;
    const int n0 = blockIdx.x * 128;

    float acc[8][8];
    #pragma unroll
    for (int i = 0; i < 8; i++)
        #pragma unroll
        for (int j = 0; j < 8; j++) acc[i][j] = 0.f;

    const int ntiles = (mode >= MODE_Z) ? 32 : 16;
    for (int kt = 0; kt < ntiles; kt++) {
        const int phase = (kt >= 16);
        const float* __restrict__ Ap = phase ? A2 : A1;
        const float* __restrict__ Bp = phase ? B2 : B1;
        const int k0 = (kt - (phase ? 16 : 0)) * 16;

        #pragma unroll
        for (int it = 0; it < 2; it++) {
            const int i  = tid + it * 256;        // 0..511
            const int r  = i >> 2;                // 0..127
            const int kq = (i & 3) << 2;          // 0,4,8,12
            float4 va = *(const float4*)&Ap[(size_t)(m0 + r)*256 + k0 + kq];
            if (mode == MODE_H && phase) {
                const float4 vr = *(const float4*)&Rm[(size_t)(m0 + r)*256 + k0 + kq];
                va.x *= vr.x; va.y *= vr.y; va.z *= vr.z; va.w *= vr.w;
            }
            As[kq  ][r] = va.x; As[kq+1][r] = va.y;
            As[kq+2][r] = va.z; As[kq+3][r] = va.w;
            const float4 vb4 = *(const float4*)&Bp[(size_t)(n0 + r)*256 + k0 + kq];
            Bs[kq  ][r] = vb4.x; Bs[kq+1][r] = vb4.y;
            Bs[kq+2][r] = vb4.z; Bs[kq+3][r] = vb4.w;
        }
        __syncthreads();

        #pragma unroll
        for (int kk = 0; kk < 16; kk++) {
            const float4 a0 = *(const float4*)&As[kk][ty*8];
            const float4 a1 = *(const float4*)&As[kk][ty*8 + 4];
            const float4 b0 = *(const float4*)&Bs[kk][tx*8];
            const float4 b1 = *(const float4*)&Bs[kk][tx*8 + 4];
            const float av[8] = {a0.x,a0.y,a0.z,a0.w,a1.x,a1.y,a1.z,a1.w};
            const float bv[8] = {b0.x,b0.y,b0.z,b0.w,b1.x,b1.y,b1.z,b1.w};
            #pragma unroll
            for (int i = 0; i < 8; i++)
                #pragma unroll
                for (int j = 0; j < 8; j++)
                    acc[i][j] = fmaf(av[i], bv[j], acc[i][j]);
        }
        __syncthreads();
    }

    if (mode == MODE_QKV) {
        // scatter bf16 into per-head q/k/v buffers
        #pragma unroll
        for (int i = 0; i < 8; i++) {
            const int m  = m0 + ty*8 + i;
            const int b_ = m >> 11;
            const int s_ = m & 2047;
            #pragma unroll
            for (int jj = 0; jj < 2; jj++) {
                const int n   = n0 + tx*8 + jj*4;   // 4-aligned, same 32-block
                const int h_  = n / 96;
                const int buf = (n >> 5) % 3;
                const int d_  = n & 31;
                const float sc = (buf == 0) ? QK_SCALE : 1.0f;
                __nv_bfloat16 e[4];
                #pragma unroll
                for (int t = 0; t < 4; t++)
                    e[t] = __float2bfloat16((acc[i][jj*4+t] + bias[n+t]) * sc);
                __nv_bfloat16* base = (buf == 0) ? qb : (buf == 1) ? kb : vb;
                const size_t dst = ((size_t)((b_*NHEAD + h_)*SEQ + s_))*HDIM + d_;
                *(uint2*)&base[dst] = *(const uint2*)e;
            }
        }
        return;
    }

    #pragma unroll
    for (int i = 0; i < 8; i++) {
        const int m = m0 + ty*8 + i;
        #pragma unroll
        for (int jj = 0; jj < 2; jj++) {
            float4 o;
            float* op = (float*)&o;
            #pragma unroll
            for (int t = 0; t < 4; t++) {
                const int n = n0 + tx*8 + jj*4 + t;
                float c = acc[i][jj*4 + t];
                if      (mode == MODE_FC)  c = fmaxf(c + bias[n], 0.f);
                else if (mode == MODE_Z)   c = 1.f/(1.f + __expf(-(c + bias[n])));
                else if (mode == MODE_R)   c = 1.f/(1.f + __expf(-c));
                else {
                    const float zz = Zb [(size_t)m*256 + n];
                    const float rs = Res[(size_t)m*256 + n];
                    c = (1.f - zz)*rs + zz*tanhf(c);
                }
                op[t] = c;
            }
            *(float4*)&C[(size_t)m*256 + n0 + tx*8 + jj*4] = o;
        }
    }
}

// ---------------------------------------------------------------------------
// bf16 tensor-core flash attention (no max-subtraction softmax).
// CTA: 8 warps, Q tile = 128 rows (16 per warp), K tile = 64, loop 32 iters.
// Grid: (S/128, H, B). Output written with the reference's head permutation.
// ---------------------------------------------------------------------------
__device__ __forceinline__ void mma16816(float* d, const uint32_t* a,
                                         uint32_t b0, uint32_t b1)
{
    asm volatile("mma.sync.aligned.m16n8k16.row.col.f32.bf16.bf16.f32 "
                 "{%0,%1,%2,%3},{%4,%5,%6,%7},{%8,%9},{%0,%1,%2,%3};\n"
                 : "+f"(d[0]), "+f"(d[1]), "+f"(d[2]), "+f"(d[3])
                 : "r"(a[0]), "r"(a[1]), "r"(a[2]), "r"(a[3]),
                   "r"(b0), "r"(b1));
}

__device__ __forceinline__ uint32_t pack_bf16x2(float lo, float hi)
{
    uint32_t r;
    asm("cvt.rn.bf16x2.f32 %0, %1, %2;" : "=r"(r) : "f"(hi), "f"(lo));
    return r;
}

#define KS_STRIDE 36   // words per K smem row (32 bf16 data + pad), conflict-free
#define VP_STRIDE 36   // words per Vp smem row

__global__ void __launch_bounds__(256, 2)
attn_mma(const __nv_bfloat16* __restrict__ q,
         const __nv_bfloat16* __restrict__ k,
         const __nv_bfloat16* __restrict__ v,
         const uint32_t* __restrict__ mask,
         float* __restrict__ outp)
{
    const int tid  = threadIdx.x;
    const int lane = tid & 31;
    const int w    = tid >> 5;          // warp 0..7
    const int h    = blockIdx.y;
    const int b    = blockIdx.z;
    const int q0   = blockIdx.x * 128;

    const size_t nb = (size_t)(b*NHEAD + h) * SEQ;   // head-batch base row
    const int gr = w*16 + (lane >> 2);               // this thread's low q-row (0..127)
    const int c2 = (lane & 3) * 2;

    __shared__ uint32_t Ks[64 * KS_STRIDE];  // K tile [64 k][32 d] bf16, padded
    __shared__ uint32_t Vp[32 * VP_STRIDE];  // V pairs: Vp[d][kp] = (V[2kp][d],V[2kp+1][d])

    // Q fragments (held for whole kernel): 2 k-tiles of m16k16
    uint32_t qa[2][4];
    {
        const __nv_bfloat16* qbase = q + (nb + q0) * HDIM;
        #pragma unroll
        for (int kt = 0; kt < 2; kt++) {
            qa[kt][0] = *(const uint32_t*)&qbase[(size_t)(gr    )*HDIM + kt*16 + c2    ];
            qa[kt][1] = *(const uint32_t*)&qbase[(size_t)(gr + 8)*HDIM + kt*16 + c2    ];
            qa[kt][2] = *(const uint32_t*)&qbase[(size_t)(gr    )*HDIM + kt*16 + c2 + 8];
            qa[kt][3] = *(const uint32_t*)&qbase[(size_t)(gr + 8)*HDIM + kt*16 + c2 + 8];
        }
    }

    const uint32_t* mrow_lo = mask + ((size_t)b*SEQ + q0 + gr) * (SEQ/32);
    const uint32_t* mrow_hi = mrow_lo + 8 * (SEQ/32);

    float o[4][4];
    #pragma unroll
    for (int i = 0; i < 4; i++)
        #pragma unroll
        for (int j = 0; j < 4; j++) o[i][j] = 0.f;
    float sum_lo = 0.f, sum_hi = 0.f;

    for (int kt = 0; kt < SEQ/64; kt++) {
        const int k0 = kt * 64;
        __syncthreads();

        // K tile: thread -> row n=tid/4, 16B chunk cw=tid%4
        {
            const int n = tid >> 2, cw = tid & 3;
            const uint4 kv = *(const uint4*)&k[(nb + k0 + n)*HDIM + cw*8];
            *(uint4*)&Ks[n*KS_STRIDE + cw*4] = kv;
        }
        // V tile, packed-transposed: thread -> pair kp=tid/8, d0=(tid%8)*4
        {
            const int kp = tid >> 3, d0 = (tid & 7) * 4;
            const uint2 r0 = *(const uint2*)&v[(nb + k0 + 2*kp    )*HDIM + d0];
            const uint2 r1 = *(const uint2*)&v[(nb + k0 + 2*kp + 1)*HDIM + d0];
            Vp[(d0    )*VP_STRIDE + kp] = __byte_perm(r0.x, r1.x, 0x5410);
            Vp[(d0 + 1)*VP_STRIDE + kp] = __byte_perm(r0.x, r1.x, 0x7632);
            Vp[(d0 + 2)*VP_STRIDE + kp] = __byte_perm(r0.y, r1.y, 0x5410);
            Vp[(d0 + 3)*VP_STRIDE + kp] = __byte_perm(r0.y, r1.y, 0x7632);
        }
        __syncthreads();

        const uint2 mlo = *(const uint2*)&mrow_lo[kt*2];
        const uint2 mhi = *(const uint2*)&mrow_hi[kt*2];

        uint32_t P0[8], P1[8];
        #pragma unroll
        for (int nt = 0; nt < 8; nt++) {
            float s[4] = {0.f, 0.f, 0.f, 0.f};
            const int nrow = (nt*8 + (lane >> 2)) * KS_STRIDE + (lane & 3);
            mma16816(s, qa[0], Ks[nrow     ], Ks[nrow +  4]);
            mma16816(s, qa[1], Ks[nrow +  8], Ks[nrow + 12]);
            // mask + exp (no max subtraction: scores are bounded)
            const uint32_t wlo = (nt < 4) ? mlo.x : mlo.y;
            const uint32_t whi = (nt < 4) ? mhi.x : mhi.y;
            const int sh = ((nt & 3) * 8) + c2;
            const uint32_t ulo = wlo >> sh;
            const uint32_t uhi = whi >> sh;
            const float p0 = (ulo & 1u) ? __expf(s[0]) : 0.f;
            const float p1 = (ulo & 2u) ? __expf(s[1]) : 0.f;
            const float p2 = (uhi & 1u) ? __expf(s[2]) : 0.f;
            const float p3 = (uhi & 2u) ? __expf(s[3]) : 0.f;
            sum_lo += p0 + p1;
            sum_hi += p2 + p3;
            P0[nt] = pack_bf16x2(p0, p1);
            P1[nt] = pack_bf16x2(p2, p3);
        }

        #pragma unroll
        for (int kt2 = 0; kt2 < 4; kt2++) {
            const uint32_t a[4] = {P0[2*kt2], P1[2*kt2], P0[2*kt2+1], P1[2*kt2+1]};
            #pragma unroll
            for (int dt = 0; dt < 4; dt++) {
                const int drow = (dt*8 + (lane >> 2)) * VP_STRIDE + kt2*8 + (lane & 3);
                mma16816(o[dt], a, Vp[drow], Vp[drow + 4]);
            }
        }
    }

    // reduce row sums over the 4 lanes sharing a row
    sum_lo += __shfl_xor_sync(0xffffffffu, sum_lo, 1);
    sum_lo += __shfl_xor_sync(0xffffffffu, sum_lo, 2);
    sum_hi += __shfl_xor_sync(0xffffffffu, sum_hi, 1);
    sum_hi += __shfl_xor_sync(0xffffffffu, sum_hi, 2);
    const float inv_lo = 1.f / sum_lo;
    const float inv_hi = 1.f / sum_hi;

    // permuted output: n = b*8+h -> batch n%4, head slot n/4
    const int n_  = b*NHEAD + h;
    const int bo  = n_ & 3;
    const int hp  = n_ >> 2;
    #pragma unroll
    for (int dt = 0; dt < 4; dt++) {
        const size_t base = ((size_t)(bo*SEQ + q0 + gr))*DIM + hp*HDIM + dt*8 + c2;
        float2 lo, hi;
        lo.x = o[dt][0]*inv_lo; lo.y = o[dt][1]*inv_lo;
        hi.x = o[dt][2]*inv_hi; hi.y = o[dt][3]*inv_hi;
        *(float2*)&outp[base]            = lo;
        *(float2*)&outp[base + 8*DIM]    = hi;
    }
}

// ---------------------------------------------------------------------------
extern "C" void kernel_launch(void* const* d_in, const int* in_sizes, int n_in,
                              void* d_out, int out_size)
{
    const float* x     = (const float*)d_in[0];
    const int*   adj   = (const int*)  d_in[1];
    const float* w_qkv = (const float*)d_in[2];
    const float* b_qkv = (const float*)d_in[3];
    const float* ln_g  = (const float*)d_in[4];
    const float* ln_b  = (const float*)d_in[5];
    const float* w_fc  = (const float*)d_in[6];
    const float* b_fc  = (const float*)d_in[7];
    const float* w_z   = (const float*)d_in[8];
    const float* b_z   = (const float*)d_in[9];
    const float* u_z   = (const float*)d_in[10];
    const float* w_r   = (const float*)d_in[11];
    const float* u_r   = (const float*)d_in[12];
    const float* w_g   = (const float*)d_in[13];
    const float* u_g   = (const float*)d_in[14];
    float* out = (float*)d_out;

    float *xn, *att, *y, *z, *r;
    __nv_bfloat16 *qb, *kb, *vb;
    uint32_t *mask;
    cudaGetSymbolAddress((void**)&xn,   g_xn);
    cudaGetSymbolAddress((void**)&att,  g_att);
    cudaGetSymbolAddress((void**)&y,    g_y);
    cudaGetSymbolAddress((void**)&z,    g_z);
    cudaGetSymbolAddress((void**)&r,    g_r);
    cudaGetSymbolAddress((void**)&qb,   g_q);
    cudaGetSymbolAddress((void**)&kb,   g_k);
    cudaGetSymbolAddress((void**)&vb,   g_v);
    cudaGetSymbolAddress((void**)&mask, g_mask);

    // 0. pack adjacency into bitmask (2MB, L2-resident)
    pack_adj<<<BATCH*SEQ*SEQ/256, 256>>>(adj, mask);
    // 1. LayerNorm
    ln_kernel<<<M_TOT, 256>>>(x, ln_g, ln_b, xn);
    // 2. QKV projection -> bf16 q/k/v per-head buffers (q pre-scaled)
    gemm128<<<dim3(6, 64), 256>>>(xn, w_qkv, nullptr, nullptr, b_qkv,
                                  nullptr, nullptr, nullptr, nullptr,
                                  qb, kb, vb, MODE_QKV);
    // 3. bf16 tensor-core flash attention (writes permuted fp32 layout)
    attn_mma<<<dim3(SEQ/128, NHEAD, BATCH), 256>>>(qb, kb, vb, mask, att);
    // 4. FC + ReLU
    gemm128<<<dim3(2, 64), 256>>>(att, w_fc, nullptr, nullptr, b_fc,
                                  nullptr, nullptr, nullptr, y,
                                  nullptr, nullptr, nullptr, MODE_FC);
    // 5. z = sigmoid(y@w_z^T + b_z + x@u_z^T)
    gemm128<<<dim3(2, 64), 256>>>(y, w_z, x, u_z, b_z,
                                  nullptr, nullptr, nullptr, z,
                                  nullptr, nullptr, nullptr, MODE_Z);
    // 6. r = sigmoid(y@w_r^T + x@u_r^T)
    gemm128<<<dim3(2, 64), 256>>>(y, w_r, x, u_r, nullptr,
                                  nullptr, nullptr, nullptr, r,
                                  nullptr, nullptr, nullptr, MODE_R);
    // 7. h_hat = tanh(y@w_g^T + (r.*x)@u_g^T); out = (1-z)*x + z*h_hat
    gemm128<<<dim3(2, 64), 256>>>(y, w_g, x, u_g, nullptr,
                                  r, z, x, out,
                                  nullptr, nullptr, nullptr, MODE_H);
}

// round 3
// speedup vs baseline: 3.7465x; 1.7609x over previous
#include <cuda_runtime.h>
#include <cuda_bf16.h>
#include <cstdint>

// Problem constants
#define SEQ   2048
#define BATCH 4
#define DIM   256
#define NHEAD 8
#define HDIM  32
#define M_TOT 8192          // BATCH*SEQ
#define QK_SCALE 0.17677669529663687f  // 1/sqrt(32)

// Scratch (device globals: allocation-free rule)
__device__ float g_xn [M_TOT*DIM];
__device__ float g_att[M_TOT*DIM];
__device__ float g_y  [M_TOT*DIM];
__device__ float g_z  [M_TOT*DIM];
__device__ float g_rx [M_TOT*DIM];
__device__ __nv_bfloat16 g_q[M_TOT*HDIM*NHEAD];   // [B*H, S, 32]
__device__ __nv_bfloat16 g_k[M_TOT*HDIM*NHEAD];
__device__ __nv_bfloat16 g_v[M_TOT*HDIM*NHEAD];
__device__ uint32_t g_mask[BATCH*SEQ*(SEQ/32)];   // 2MB bit mask

// ---------------------------------------------------------------------------
// adj -> bitmask (ballot pack)
// ---------------------------------------------------------------------------
__global__ void pack_adj(const int* __restrict__ adj, uint32_t* __restrict__ mask)
{
    const int idx = blockIdx.x * 256 + threadIdx.x;
    const int v = adj[idx];
    const uint32_t bal = __ballot_sync(0xffffffffu, v != 0);
    if ((threadIdx.x & 31) == 0) mask[idx >> 5] = bal;
}

// ---------------------------------------------------------------------------
// LayerNorm: one block per row, 256 threads
// ---------------------------------------------------------------------------
__global__ void ln_kernel(const float* __restrict__ x,
                          const float* __restrict__ gamma,
                          const float* __restrict__ beta,
                          float* __restrict__ out)
{
    const int row = blockIdx.x;
    const int tid = threadIdx.x;
    const float v = x[(size_t)row*DIM + tid];
    float s = v, s2 = v*v;
    #pragma unroll
    for (int o = 16; o; o >>= 1) {
        s  += __shfl_xor_sync(0xffffffffu, s,  o);
        s2 += __shfl_xor_sync(0xffffffffu, s2, o);
    }
    __shared__ float ps[8], ps2[8];
    if ((tid & 31) == 0) { ps[tid>>5] = s; ps2[tid>>5] = s2; }
    __syncthreads();
    float tot = 0.f, tot2 = 0.f;
    #pragma unroll
    for (int i = 0; i < 8; i++) { tot += ps[i]; tot2 += ps2[i]; }
    const float mu   = tot * (1.0f/DIM);
    const float var  = tot2 * (1.0f/DIM) - mu*mu;
    const float rstd = rsqrtf(var + 1e-5f);
    out[(size_t)row*DIM + tid] = (v - mu) * rstd * gamma[tid] + beta[tid];
}

// ---------------------------------------------------------------------------
// tf32 tensor-core GEMM. CTA tile 128(M) x 64(N), k-tile 32, 8 warps (32x32).
// C[m,n] = sum_k A[m,k]*B[n,k]. K = KT*32 (phase 1 = second source at k>=256).
// Modes:
//   0 QKV: A=xn, B=w_qkv[768,256]; epi: bf16 scatter q(*scale)/k/v
//   1 FC : A=att, B=w_fc; epi: relu(+bias) -> y
//   2 ZR : A=[y|x], B(nhalf0)=[w_z|u_z], B(nhalf1)=[w_r|u_r];
//          epi n<256: z=sigmoid(acc+b_z[n]) -> Cz ; n>=256: rx=sigmoid(acc)*X -> Crx
//   3 H  : A=[y|rx], B=[w_g|u_g]; epi: (1-z)*X + z*tanh(acc) -> out
// ---------------------------------------------------------------------------
enum { MODE_QKV = 0, MODE_FC = 1, MODE_ZR = 2, MODE_H = 3 };

__device__ __forceinline__ uint32_t f2tf32(float f)
{
    uint32_t r;
    asm("cvt.rna.tf32.f32 %0, %1;" : "=r"(r) : "f"(f));
    return r;
}

__device__ __forceinline__ void mma_tf32(float* d, const uint32_t* a,
                                         uint32_t b0, uint32_t b1)
{
    asm volatile("mma.sync.aligned.m16n8k8.row.col.f32.tf32.tf32.f32 "
                 "{%0,%1,%2,%3},{%4,%5,%6,%7},{%8,%9},{%0,%1,%2,%3};\n"
                 : "+f"(d[0]), "+f"(d[1]), "+f"(d[2]), "+f"(d[3])
                 : "r"(a[0]), "r"(a[1]), "r"(a[2]), "r"(a[3]),
                   "r"(b0), "r"(b1));
}

__device__ __forceinline__ uint32_t pack_bf16x2(float lo, float hi)
{
    uint32_t r;
    asm("cvt.rn.bf16x2.f32 %0, %1, %2;" : "=r"(r) : "f"(hi), "f"(lo));
    return r;
}

#define AST 36   // smem row stride (words): (r*36 + c) % 32 = 4r+c -> conflict-free

__global__ void __launch_bounds__(256)
gemm_tc(const float* __restrict__ A1, const float* __restrict__ A2,
        const float* __restrict__ B00, const float* __restrict__ B01,
        const float* __restrict__ B10, const float* __restrict__ B11,
        const float* __restrict__ bias,
        const float* __restrict__ X,     // residual x (ZR rx-mult, H residual)
        const float* __restrict__ Zb,    // z (H)
        float* __restrict__ C,
        float* __restrict__ Crx,         // rx output (ZR)
        __nv_bfloat16* __restrict__ qb,
        __nv_bfloat16* __restrict__ kb,
        __nv_bfloat16* __restrict__ vb,
        int mode, int KT)
{
    __shared__ uint32_t As[128*AST];
    __shared__ uint32_t Bs[64*AST];

    const int tid  = threadIdx.x;
    const int lane = tid & 31;
    const int w    = tid >> 5;
    const int wm   = w >> 1, wn = w & 1;
    const int m0   = blockIdx.y * 128;
    const int n0   = blockIdx.x * 64;
    const int half = (mode == MODE_ZR && n0 >= 256) ? 1 : 0;
    const int brow0 = n0 - (half ? 256 : 0);

    float acc[8][4];
    #pragma unroll
    for (int i = 0; i < 8; i++)
        #pragma unroll
        for (int j = 0; j < 4; j++) acc[i][j] = 0.f;

    float4 pa[4], pb[2];

    // prefetch tile 0
    {
        const float* Ap = A1;
        const float* Bp = half ? B10 : B00;
        #pragma unroll
        for (int it = 0; it < 4; it++) {
            const int lin = tid + it*256, r = lin >> 3, cq = (lin & 7) * 4;
            pa[it] = *(const float4*)&Ap[(size_t)(m0 + r)*256 + cq];
        }
        #pragma unroll
        for (int it = 0; it < 2; it++) {
            const int lin = tid + it*256, r = lin >> 3, cq = (lin & 7) * 4;
            pb[it] = *(const float4*)&Bp[(size_t)(brow0 + r)*256 + cq];
        }
    }

    for (int kt = 0; kt < KT; kt++) {
        // store prefetched tile to smem (with tf32 conversion)
        #pragma unroll
        for (int it = 0; it < 4; it++) {
            const int lin = tid + it*256, r = lin >> 3, cq = (lin & 7) * 4;
            uint32_t* d = &As[r*AST + cq];
            d[0] = f2tf32(pa[it].x); d[1] = f2tf32(pa[it].y);
            d[2] = f2tf32(pa[it].z); d[3] = f2tf32(pa[it].w);
        }
        #pragma unroll
        for (int it = 0; it < 2; it++) {
            const int lin = tid + it*256, r = lin >> 3, cq = (lin & 7) * 4;
            uint32_t* d = &Bs[r*AST + cq];
            d[0] = f2tf32(pb[it].x); d[1] = f2tf32(pb[it].y);
            d[2] = f2tf32(pb[it].z); d[3] = f2tf32(pb[it].w);
        }
        __syncthreads();

        // prefetch next tile
        if (kt + 1 < KT) {
            const int kg    = (kt + 1) * 32;
            const int phase = kg >= 256;
            const int k0    = kg & 255;
            const float* Ap = phase ? A2 : A1;
            const float* Bp = half ? (phase ? B11 : B10) : (phase ? B01 : B00);
            #pragma unroll
            for (int it = 0; it < 4; it++) {
                const int lin = tid + it*256, r = lin >> 3, cq = (lin & 7) * 4;
                pa[it] = *(const float4*)&Ap[(size_t)(m0 + r)*256 + k0 + cq];
            }
            #pragma unroll
            for (int it = 0; it < 2; it++) {
                const int lin = tid + it*256, r = lin >> 3, cq = (lin & 7) * 4;
                pb[it] = *(const float4*)&Bp[(size_t)(brow0 + r)*256 + k0 + cq];
            }
        }

        // compute: 4 x k8 steps
        #pragma unroll
        for (int k8 = 0; k8 < 4; k8++) {
            const int kc = k8*8 + (lane & 3);
            uint32_t a[2][4], bf[4][2];
            #pragma unroll
            for (int tm = 0; tm < 2; tm++) {
                const int row = wm*32 + tm*16 + (lane >> 2);
                a[tm][0] = As[ row     *AST + kc    ];
                a[tm][1] = As[(row + 8)*AST + kc    ];
                a[tm][2] = As[ row     *AST + kc + 4];
                a[tm][3] = As[(row + 8)*AST + kc + 4];
            }
            #pragma unroll
            for (int tn = 0; tn < 4; tn++) {
                const int nrow = wn*32 + tn*8 + (lane >> 2);
                bf[tn][0] = Bs[nrow*AST + kc    ];
                bf[tn][1] = Bs[nrow*AST + kc + 4];
            }
            #pragma unroll
            for (int tm = 0; tm < 2; tm++)
                #pragma unroll
                for (int tn = 0; tn < 4; tn++)
                    mma_tf32(acc[tm*4 + tn], a[tm], bf[tn][0], bf[tn][1]);
        }
        __syncthreads();
    }

    // -------- epilogue --------
    const int rbase = m0 + wm*32 + (lane >> 2);
    const int cbase = n0 + wn*32 + 2*(lane & 3);

    #pragma unroll
    for (int tm = 0; tm < 2; tm++) {
        #pragma unroll
        for (int tn = 0; tn < 4; tn++) {
            const float* ac = acc[tm*4 + tn];
            const int c = cbase + tn*8;
            #pragma unroll
            for (int hrow = 0; hrow < 2; hrow++) {
                const int m = rbase + tm*16 + hrow*8;
                const float v0 = ac[hrow*2], v1 = ac[hrow*2 + 1];
                if (mode == MODE_QKV) {
                    const int b_ = m >> 11, s_ = m & 2047;
                    const int h_ = c / 96, buf = (c >> 5) % 3, d_ = c & 31;
                    const float sc = (buf == 0) ? QK_SCALE : 1.0f;
                    const uint32_t pk = pack_bf16x2((v0 + bias[c])*sc,
                                                    (v1 + bias[c+1])*sc);
                    __nv_bfloat16* base = (buf == 0) ? qb : (buf == 1) ? kb : vb;
                    *(uint32_t*)&base[((size_t)((b_*NHEAD + h_)*SEQ + s_))*HDIM + d_] = pk;
                } else if (mode == MODE_FC) {
                    float2 o;
                    o.x = fmaxf(v0 + bias[c],   0.f);
                    o.y = fmaxf(v1 + bias[c+1], 0.f);
                    *(float2*)&C[(size_t)m*256 + c] = o;
                } else if (mode == MODE_ZR) {
                    if (!half) {
                        float2 o;
                        o.x = 1.f/(1.f + __expf(-(v0 + bias[c])));
                        o.y = 1.f/(1.f + __expf(-(v1 + bias[c+1])));
                        *(float2*)&C[(size_t)m*256 + c] = o;
                    } else {
                        const int nc = c - 256;
                        const float2 xv = *(const float2*)&X[(size_t)m*256 + nc];
                        float2 o;
                        o.x = xv.x / (1.f + __expf(-v0));
                        o.y = xv.y / (1.f + __expf(-v1));
                        *(float2*)&Crx[(size_t)m*256 + nc] = o;
                    }
                } else { // MODE_H
                    const float2 zz = *(const float2*)&Zb[(size_t)m*256 + c];
                    const float2 xv = *(const float2*)&X [(size_t)m*256 + c];
                    float2 o;
                    o.x = (1.f - zz.x)*xv.x + zz.x*tanhf(v0);
                    o.y = (1.f - zz.y)*xv.y + zz.y*tanhf(v1);
                    *(float2*)&C[(size_t)m*256 + c] = o;
                }
            }
        }
    }
}

// ---------------------------------------------------------------------------
// bf16 tensor-core flash attention (no max-subtraction softmax). Unchanged.
// ---------------------------------------------------------------------------
__device__ __forceinline__ void mma16816(float* d, const uint32_t* a,
                                         uint32_t b0, uint32_t b1)
{
    asm volatile("mma.sync.aligned.m16n8k16.row.col.f32.bf16.bf16.f32 "
                 "{%0,%1,%2,%3},{%4,%5,%6,%7},{%8,%9},{%0,%1,%2,%3};\n"
                 : "+f"(d[0]), "+f"(d[1]), "+f"(d[2]), "+f"(d[3])
                 : "r"(a[0]), "r"(a[1]), "r"(a[2]), "r"(a[3]),
                   "r"(b0), "r"(b1));
}

#define KS_STRIDE 36
#define VP_STRIDE 36

__global__ void __launch_bounds__(256, 2)
attn_mma(const __nv_bfloat16* __restrict__ q,
         const __nv_bfloat16* __restrict__ k,
         const __nv_bfloat16* __restrict__ v,
         const uint32_t* __restrict__ mask,
         float* __restrict__ outp)
{
    const int tid  = threadIdx.x;
    const int lane = tid & 31;
    const int w    = tid >> 5;
    const int h    = blockIdx.y;
    const int b    = blockIdx.z;
    const int q0   = blockIdx.x * 128;

    const size_t nb = (size_t)(b*NHEAD + h) * SEQ;
    const int gr = w*16 + (lane >> 2);
    const int c2 = (lane & 3) * 2;

    __shared__ uint32_t Ks[64 * KS_STRIDE];
    __shared__ uint32_t Vp[32 * VP_STRIDE];

    uint32_t qa[2][4];
    {
        const __nv_bfloat16* qbase = q + (nb + q0) * HDIM;
        #pragma unroll
        for (int kt = 0; kt < 2; kt++) {
            qa[kt][0] = *(const uint32_t*)&qbase[(size_t)(gr    )*HDIM + kt*16 + c2    ];
            qa[kt][1] = *(const uint32_t*)&qbase[(size_t)(gr + 8)*HDIM + kt*16 + c2    ];
            qa[kt][2] = *(const uint32_t*)&qbase[(size_t)(gr    )*HDIM + kt*16 + c2 + 8];
            qa[kt][3] = *(const uint32_t*)&qbase[(size_t)(gr + 8)*HDIM + kt*16 + c2 + 8];
        }
    }

    const uint32_t* mrow_lo = mask + ((size_t)b*SEQ + q0 + gr) * (SEQ/32);
    const uint32_t* mrow_hi = mrow_lo + 8 * (SEQ/32);

    float o[4][4];
    #pragma unroll
    for (int i = 0; i < 4; i++)
        #pragma unroll
        for (int j = 0; j < 4; j++) o[i][j] = 0.f;
    float sum_lo = 0.f, sum_hi = 0.f;

    for (int kt = 0; kt < SEQ/64; kt++) {
        const int k0 = kt * 64;
        __syncthreads();

        {
            const int n = tid >> 2, cw = tid & 3;
            const uint4 kv = *(const uint4*)&k[(nb + k0 + n)*HDIM + cw*8];
            *(uint4*)&Ks[n*KS_STRIDE + cw*4] = kv;
        }
        {
            const int kp = tid >> 3, d0 = (tid & 7) * 4;
            const uint2 r0 = *(const uint2*)&v[(nb + k0 + 2*kp    )*HDIM + d0];
            const uint2 r1 = *(const uint2*)&v[(nb + k0 + 2*kp + 1)*HDIM + d0];
            Vp[(d0    )*VP_STRIDE + kp] = __byte_perm(r0.x, r1.x, 0x5410);
            Vp[(d0 + 1)*VP_STRIDE + kp] = __byte_perm(r0.x, r1.x, 0x7632);
            Vp[(d0 + 2)*VP_STRIDE + kp] = __byte_perm(r0.y, r1.y, 0x5410);
            Vp[(d0 + 3)*VP_STRIDE + kp] = __byte_perm(r0.y, r1.y, 0x7632);
        }
        __syncthreads();

        const uint2 mlo = *(const uint2*)&mrow_lo[kt*2];
        const uint2 mhi = *(const uint2*)&mrow_hi[kt*2];

        uint32_t P0[8], P1[8];
        #pragma unroll
        for (int nt = 0; nt < 8; nt++) {
            float s[4] = {0.f, 0.f, 0.f, 0.f};
            const int nrow = (nt*8 + (lane >> 2)) * KS_STRIDE + (lane & 3);
            mma16816(s, qa[0], Ks[nrow     ], Ks[nrow +  4]);
            mma16816(s, qa[1], Ks[nrow +  8], Ks[nrow + 12]);
            const uint32_t wlo = (nt < 4) ? mlo.x : mlo.y;
            const uint32_t whi = (nt < 4) ? mhi.x : mhi.y;
            const int sh = ((nt & 3) * 8) + c2;
            const uint32_t ulo = wlo >> sh;
            const uint32_t uhi = whi >> sh;
            const float p0 = (ulo & 1u) ? __expf(s[0]) : 0.f;
            const float p1 = (ulo & 2u) ? __expf(s[1]) : 0.f;
            const float p2 = (uhi & 1u) ? __expf(s[2]) : 0.f;
            const float p3 = (uhi & 2u) ? __expf(s[3]) : 0.f;
            sum_lo += p0 + p1;
            sum_hi += p2 + p3;
            P0[nt] = pack_bf16x2(p0, p1);
            P1[nt] = pack_bf16x2(p2, p3);
        }

        #pragma unroll
        for (int kt2 = 0; kt2 < 4; kt2++) {
            const uint32_t a[4] = {P0[2*kt2], P1[2*kt2], P0[2*kt2+1], P1[2*kt2+1]};
            #pragma unroll
            for (int dt = 0; dt < 4; dt++) {
                const int drow = (dt*8 + (lane >> 2)) * VP_STRIDE + kt2*8 + (lane & 3);
                mma16816(o[dt], a, Vp[drow], Vp[drow + 4]);
            }
        }
    }

    sum_lo += __shfl_xor_sync(0xffffffffu, sum_lo, 1);
    sum_lo += __shfl_xor_sync(0xffffffffu, sum_lo, 2);
    sum_hi += __shfl_xor_sync(0xffffffffu, sum_hi, 1);
    sum_hi += __shfl_xor_sync(0xffffffffu, sum_hi, 2);
    const float inv_lo = 1.f / sum_lo;
    const float inv_hi = 1.f / sum_hi;

    const int n_  = b*NHEAD + h;
    const int bo  = n_ & 3;
    const int hp  = n_ >> 2;
    #pragma unroll
    for (int dt = 0; dt < 4; dt++) {
        const size_t base = ((size_t)(bo*SEQ + q0 + gr))*DIM + hp*HDIM + dt*8 + c2;
        float2 lo, hi;
        lo.x = o[dt][0]*inv_lo; lo.y = o[dt][1]*inv_lo;
        hi.x = o[dt][2]*inv_hi; hi.y = o[dt][3]*inv_hi;
        *(float2*)&outp[base]         = lo;
        *(float2*)&outp[base + 8*DIM] = hi;
    }
}

// ---------------------------------------------------------------------------
extern "C" void kernel_launch(void* const* d_in, const int* in_sizes, int n_in,
                              void* d_out, int out_size)
{
    const float* x     = (const float*)d_in[0];
    const int*   adj   = (const int*)  d_in[1];
    const float* w_qkv = (const float*)d_in[2];
    const float* b_qkv = (const float*)d_in[3];
    const float* ln_g  = (const float*)d_in[4];
    const float* ln_b  = (const float*)d_in[5];
    const float* w_fc  = (const float*)d_in[6];
    const float* b_fc  = (const float*)d_in[7];
    const float* w_z   = (const float*)d_in[8];
    const float* b_z   = (const float*)d_in[9];
    const float* u_z   = (const float*)d_in[10];
    const float* w_r   = (const float*)d_in[11];
    const float* u_r   = (const float*)d_in[12];
    const float* w_g   = (const float*)d_in[13];
    const float* u_g   = (const float*)d_in[14];
    float* out = (float*)d_out;

    float *xn, *att, *y, *z, *rx;
    __nv_bfloat16 *qb, *kb, *vb;
    uint32_t *mask;
    cudaGetSymbolAddress((void**)&xn,   g_xn);
    cudaGetSymbolAddress((void**)&att,  g_att);
    cudaGetSymbolAddress((void**)&y,    g_y);
    cudaGetSymbolAddress((void**)&z,    g_z);
    cudaGetSymbolAddress((void**)&rx,   g_rx);
    cudaGetSymbolAddress((void**)&qb,   g_q);
    cudaGetSymbolAddress((void**)&kb,   g_k);
    cudaGetSymbolAddress((void**)&vb,   g_v);
    cudaGetSymbolAddress((void**)&mask, g_mask);

    // 0. pack adjacency into bitmask
    pack_adj<<<BATCH*SEQ*SEQ/256, 256>>>(adj, mask);
    // 1. LayerNorm
    ln_kernel<<<M_TOT, 256>>>(x, ln_g, ln_b, xn);
    // 2. QKV projection (tf32 TC) -> bf16 q/k/v per-head buffers
    gemm_tc<<<dim3(12, 64), 256>>>(xn, nullptr, w_qkv, nullptr, nullptr, nullptr,
                                   b_qkv, nullptr, nullptr,
                                   nullptr, nullptr, qb, kb, vb, MODE_QKV, 8);
    // 3. bf16 tensor-core flash attention
    attn_mma<<<dim3(SEQ/128, NHEAD, BATCH), 256>>>(qb, kb, vb, mask, att);
    // 4. FC + ReLU (tf32 TC)
    gemm_tc<<<dim3(4, 64), 256>>>(att, nullptr, w_fc, nullptr, nullptr, nullptr,
                                  b_fc, nullptr, nullptr,
                                  y, nullptr, nullptr, nullptr, nullptr, MODE_FC, 8);
    // 5. fused ZR: z = sigmoid(y@w_z^T+b_z+x@u_z^T); rx = sigmoid(y@w_r^T+x@u_r^T)*x
    gemm_tc<<<dim3(8, 64), 256>>>(y, x, w_z, u_z, w_r, u_r,
                                  b_z, x, nullptr,
                                  z, rx, nullptr, nullptr, nullptr, MODE_ZR, 16);
    // 6. H: out = (1-z)*x + z*tanh(y@w_g^T + rx@u_g^T)
    gemm_tc<<<dim3(4, 64), 256>>>(y, rx, w_g, u_g, nullptr, nullptr,
                                  nullptr, x, z,
                                  out, nullptr, nullptr, nullptr, nullptr, MODE_H, 16);
}

// round 4
// speedup vs baseline: 3.9296x; 1.0489x over previous
#include <cuda_runtime.h>
#include <cuda_bf16.h>
#include <cstdint>

// Problem constants
#define SEQ   2048
#define BATCH 4
#define DIM   256
#define NHEAD 8
#define HDIM  32
#define M_TOT 8192          // BATCH*SEQ
#define QK_SCALE 0.17677669529663687f  // 1/sqrt(32)

// Scratch (device globals: allocation-free rule)
__device__ float g_xn [M_TOT*DIM];
__device__ float g_att[M_TOT*DIM];
__device__ float g_y  [M_TOT*DIM];
__device__ float g_z  [M_TOT*DIM];
__device__ float g_rx [M_TOT*DIM];
__device__ __nv_bfloat16 g_q[M_TOT*HDIM*NHEAD];   // [B*H, S, 32]
__device__ __nv_bfloat16 g_k[M_TOT*HDIM*NHEAD];
__device__ __nv_bfloat16 g_v[M_TOT*HDIM*NHEAD];
__device__ uint32_t g_mask[BATCH*SEQ*(SEQ/32)];   // 2MB bit mask

// ---------------------------------------------------------------------------
// adj -> bitmask (ballot pack)
// ---------------------------------------------------------------------------
__global__ void pack_adj(const int* __restrict__ adj, uint32_t* __restrict__ mask)
{
    const int idx = blockIdx.x * 256 + threadIdx.x;
    const int v = adj[idx];
    const uint32_t bal = __ballot_sync(0xffffffffu, v != 0);
    if ((threadIdx.x & 31) == 0) mask[idx >> 5] = bal;
}

// ---------------------------------------------------------------------------
// LayerNorm: one block per row, 256 threads
// ---------------------------------------------------------------------------
__global__ void ln_kernel(const float* __restrict__ x,
                          const float* __restrict__ gamma,
                          const float* __restrict__ beta,
                          float* __restrict__ out)
{
    const int row = blockIdx.x;
    const int tid = threadIdx.x;
    const float v = x[(size_t)row*DIM + tid];
    float s = v, s2 = v*v;
    #pragma unroll
    for (int o = 16; o; o >>= 1) {
        s  += __shfl_xor_sync(0xffffffffu, s,  o);
        s2 += __shfl_xor_sync(0xffffffffu, s2, o);
    }
    __shared__ float ps[8], ps2[8];
    if ((tid & 31) == 0) { ps[tid>>5] = s; ps2[tid>>5] = s2; }
    __syncthreads();
    float tot = 0.f, tot2 = 0.f;
    #pragma unroll
    for (int i = 0; i < 8; i++) { tot += ps[i]; tot2 += ps2[i]; }
    const float mu   = tot * (1.0f/DIM);
    const float var  = tot2 * (1.0f/DIM) - mu*mu;
    const float rstd = rsqrtf(var + 1e-5f);
    out[(size_t)row*DIM + tid] = (v - mu) * rstd * gamma[tid] + beta[tid];
}

// ---------------------------------------------------------------------------
// tf32 tensor-core GEMM (unchanged from round 3).
// ---------------------------------------------------------------------------
enum { MODE_QKV = 0, MODE_FC = 1, MODE_ZR = 2, MODE_H = 3 };

__device__ __forceinline__ uint32_t f2tf32(float f)
{
    uint32_t r;
    asm("cvt.rna.tf32.f32 %0, %1;" : "=r"(r) : "f"(f));
    return r;
}

__device__ __forceinline__ void mma_tf32(float* d, const uint32_t* a,
                                         uint32_t b0, uint32_t b1)
{
    asm volatile("mma.sync.aligned.m16n8k8.row.col.f32.tf32.tf32.f32 "
                 "{%0,%1,%2,%3},{%4,%5,%6,%7},{%8,%9},{%0,%1,%2,%3};\n"
                 : "+f"(d[0]), "+f"(d[1]), "+f"(d[2]), "+f"(d[3])
                 : "r"(a[0]), "r"(a[1]), "r"(a[2]), "r"(a[3]),
                   "r"(b0), "r"(b1));
}

__device__ __forceinline__ uint32_t pack_bf16x2(float lo, float hi)
{
    uint32_t r;
    asm("cvt.rn.bf16x2.f32 %0, %1, %2;" : "=r"(r) : "f"(hi), "f"(lo));
    return r;
}

#define AST 36

__global__ void __launch_bounds__(256)
gemm_tc(const float* __restrict__ A1, const float* __restrict__ A2,
        const float* __restrict__ B00, const float* __restrict__ B01,
        const float* __restrict__ B10, const float* __restrict__ B11,
        const float* __restrict__ bias,
        const float* __restrict__ X,
        const float* __restrict__ Zb,
        float* __restrict__ C,
        float* __restrict__ Crx,
        __nv_bfloat16* __restrict__ qb,
        __nv_bfloat16* __restrict__ kb,
        __nv_bfloat16* __restrict__ vb,
        int mode, int KT)
{
    __shared__ uint32_t As[128*AST];
    __shared__ uint32_t Bs[64*AST];

    const int tid  = threadIdx.x;
    const int lane = tid & 31;
    const int w    = tid >> 5;
    const int wm   = w >> 1, wn = w & 1;
    const int m0   = blockIdx.y * 128;
    const int n0   = blockIdx.x * 64;
    const int half = (mode == MODE_ZR && n0 >= 256) ? 1 : 0;
    const int brow0 = n0 - (half ? 256 : 0);

    float acc[8][4];
    #pragma unroll
    for (int i = 0; i < 8; i++)
        #pragma unroll
        for (int j = 0; j < 4; j++) acc[i][j] = 0.f;

    float4 pa[4], pb[2];

    {
        const float* Ap = A1;
        const float* Bp = half ? B10 : B00;
        #pragma unroll
        for (int it = 0; it < 4; it++) {
            const int lin = tid + it*256, r = lin >> 3, cq = (lin & 7) * 4;
            pa[it] = *(const float4*)&Ap[(size_t)(m0 + r)*256 + cq];
        }
        #pragma unroll
        for (int it = 0; it < 2; it++) {
            const int lin = tid + it*256, r = lin >> 3, cq = (lin & 7) * 4;
            pb[it] = *(const float4*)&Bp[(size_t)(brow0 + r)*256 + cq];
        }
    }

    for (int kt = 0; kt < KT; kt++) {
        #pragma unroll
        for (int it = 0; it < 4; it++) {
            const int lin = tid + it*256, r = lin >> 3, cq = (lin & 7) * 4;
            uint32_t* d = &As[r*AST + cq];
            d[0] = f2tf32(pa[it].x); d[1] = f2tf32(pa[it].y);
            d[2] = f2tf32(pa[it].z); d[3] = f2tf32(pa[it].w);
        }
        #pragma unroll
        for (int it = 0; it < 2; it++) {
            const int lin = tid + it*256, r = lin >> 3, cq = (lin & 7) * 4;
            uint32_t* d = &Bs[r*AST + cq];
            d[0] = f2tf32(pb[it].x); d[1] = f2tf32(pb[it].y);
            d[2] = f2tf32(pb[it].z); d[3] = f2tf32(pb[it].w);
        }
        __syncthreads();

        if (kt + 1 < KT) {
            const int kg    = (kt + 1) * 32;
            const int phase = kg >= 256;
            const int k0    = kg & 255;
            const float* Ap = phase ? A2 : A1;
            const float* Bp = half ? (phase ? B11 : B10) : (phase ? B01 : B00);
            #pragma unroll
            for (int it = 0; it < 4; it++) {
                const int lin = tid + it*256, r = lin >> 3, cq = (lin & 7) * 4;
                pa[it] = *(const float4*)&Ap[(size_t)(m0 + r)*256 + k0 + cq];
            }
            #pragma unroll
            for (int it = 0; it < 2; it++) {
                const int lin = tid + it*256, r = lin >> 3, cq = (lin & 7) * 4;
                pb[it] = *(const float4*)&Bp[(size_t)(brow0 + r)*256 + k0 + cq];
            }
        }

        #pragma unroll
        for (int k8 = 0; k8 < 4; k8++) {
            const int kc = k8*8 + (lane & 3);
            uint32_t a[2][4], bf[4][2];
            #pragma unroll
            for (int tm = 0; tm < 2; tm++) {
                const int row = wm*32 + tm*16 + (lane >> 2);
                a[tm][0] = As[ row     *AST + kc    ];
                a[tm][1] = As[(row + 8)*AST + kc    ];
                a[tm][2] = As[ row     *AST + kc + 4];
                a[tm][3] = As[(row + 8)*AST + kc + 4];
            }
            #pragma unroll
            for (int tn = 0; tn < 4; tn++) {
                const int nrow = wn*32 + tn*8 + (lane >> 2);
                bf[tn][0] = Bs[nrow*AST + kc    ];
                bf[tn][1] = Bs[nrow*AST + kc + 4];
            }
            #pragma unroll
            for (int tm = 0; tm < 2; tm++)
                #pragma unroll
                for (int tn = 0; tn < 4; tn++)
                    mma_tf32(acc[tm*4 + tn], a[tm], bf[tn][0], bf[tn][1]);
        }
        __syncthreads();
    }

    const int rbase = m0 + wm*32 + (lane >> 2);
    const int cbase = n0 + wn*32 + 2*(lane & 3);

    #pragma unroll
    for (int tm = 0; tm < 2; tm++) {
        #pragma unroll
        for (int tn = 0; tn < 4; tn++) {
            const float* ac = acc[tm*4 + tn];
            const int c = cbase + tn*8;
            #pragma unroll
            for (int hrow = 0; hrow < 2; hrow++) {
                const int m = rbase + tm*16 + hrow*8;
                const float v0 = ac[hrow*2], v1 = ac[hrow*2 + 1];
                if (mode == MODE_QKV) {
                    const int b_ = m >> 11, s_ = m & 2047;
                    const int h_ = c / 96, buf = (c >> 5) % 3, d_ = c & 31;
                    const float sc = (buf == 0) ? QK_SCALE : 1.0f;
                    const uint32_t pk = pack_bf16x2((v0 + bias[c])*sc,
                                                    (v1 + bias[c+1])*sc);
                    __nv_bfloat16* base = (buf == 0) ? qb : (buf == 1) ? kb : vb;
                    *(uint32_t*)&base[((size_t)((b_*NHEAD + h_)*SEQ + s_))*HDIM + d_] = pk;
                } else if (mode == MODE_FC) {
                    float2 o;
                    o.x = fmaxf(v0 + bias[c],   0.f);
                    o.y = fmaxf(v1 + bias[c+1], 0.f);
                    *(float2*)&C[(size_t)m*256 + c] = o;
                } else if (mode == MODE_ZR) {
                    if (!half) {
                        float2 o;
                        o.x = 1.f/(1.f + __expf(-(v0 + bias[c])));
                        o.y = 1.f/(1.f + __expf(-(v1 + bias[c+1])));
                        *(float2*)&C[(size_t)m*256 + c] = o;
                    } else {
                        const int nc = c - 256;
                        const float2 xv = *(const float2*)&X[(size_t)m*256 + nc];
                        float2 o;
                        o.x = xv.x / (1.f + __expf(-v0));
                        o.y = xv.y / (1.f + __expf(-v1));
                        *(float2*)&Crx[(size_t)m*256 + nc] = o;
                    }
                } else {
                    const float2 zz = *(const float2*)&Zb[(size_t)m*256 + c];
                    const float2 xv = *(const float2*)&X [(size_t)m*256 + c];
                    float2 o;
                    o.x = (1.f - zz.x)*xv.x + zz.x*tanhf(v0);
                    o.y = (1.f - zz.y)*xv.y + zz.y*tanhf(v1);
                    *(float2*)&C[(size_t)m*256 + c] = o;
                }
            }
        }
    }
}

// ---------------------------------------------------------------------------
// bf16 tensor-core flash attention v2:
//   - ldmatrix.x4 fragment loads (replaces 64 scalar LDS + index math / k-tile)
//   - double-buffered K/V/mask tiles, register prefetch, 1 sync per iteration
// ---------------------------------------------------------------------------
__device__ __forceinline__ void mma16816(float* d, const uint32_t* a,
                                         uint32_t b0, uint32_t b1)
{
    asm volatile("mma.sync.aligned.m16n8k16.row.col.f32.bf16.bf16.f32 "
                 "{%0,%1,%2,%3},{%4,%5,%6,%7},{%8,%9},{%0,%1,%2,%3};\n"
                 : "+f"(d[0]), "+f"(d[1]), "+f"(d[2]), "+f"(d[3])
                 : "r"(a[0]), "r"(a[1]), "r"(a[2]), "r"(a[3]),
                   "r"(b0), "r"(b1));
}

__device__ __forceinline__ void ldmx4(uint32_t& r0, uint32_t& r1,
                                      uint32_t& r2, uint32_t& r3, uint32_t addr)
{
    asm volatile("ldmatrix.sync.aligned.m8n8.x4.shared.b16 {%0,%1,%2,%3},[%4];"
                 : "=r"(r0), "=r"(r1), "=r"(r2), "=r"(r3) : "r"(addr));
}

#define KS_STRIDE 36
#define VP_STRIDE 36
#define KS_WORDS  (64*KS_STRIDE)   // per-buffer words
#define VP_WORDS  (32*VP_STRIDE)

__global__ void __launch_bounds__(256, 2)
attn_mma(const __nv_bfloat16* __restrict__ q,
         const __nv_bfloat16* __restrict__ k,
         const __nv_bfloat16* __restrict__ v,
         const uint32_t* __restrict__ mask,
         float* __restrict__ outp)
{
    const int tid  = threadIdx.x;
    const int lane = tid & 31;
    const int w    = tid >> 5;
    const int h    = blockIdx.y;
    const int b    = blockIdx.z;
    const int q0   = blockIdx.x * 128;

    const size_t nb = (size_t)(b*NHEAD + h) * SEQ;
    const int gr = w*16 + (lane >> 2);
    const int c2 = (lane & 3) * 2;

    __shared__ uint32_t Ks[2][KS_WORDS];
    __shared__ uint32_t Vp[2][VP_WORDS];

    // Q fragments (held for whole kernel)
    uint32_t qa[2][4];
    {
        const __nv_bfloat16* qbase = q + (nb + q0) * HDIM;
        #pragma unroll
        for (int kt = 0; kt < 2; kt++) {
            qa[kt][0] = *(const uint32_t*)&qbase[(size_t)(gr    )*HDIM + kt*16 + c2    ];
            qa[kt][1] = *(const uint32_t*)&qbase[(size_t)(gr + 8)*HDIM + kt*16 + c2    ];
            qa[kt][2] = *(const uint32_t*)&qbase[(size_t)(gr    )*HDIM + kt*16 + c2 + 8];
            qa[kt][3] = *(const uint32_t*)&qbase[(size_t)(gr + 8)*HDIM + kt*16 + c2 + 8];
        }
    }

    // global-load coordinates
    const int kn  = tid >> 2, kc  = tid & 3;       // K: row, 16B chunk
    const int vkp = tid >> 3, vd0 = (tid & 7) * 4; // V: key-pair, d-base
    const __nv_bfloat16* kgp = k + (nb + kn   )*HDIM + kc*8;
    const __nv_bfloat16* vg0 = v + (nb + 2*vkp    )*HDIM + vd0;
    const __nv_bfloat16* vg1 = v + (nb + 2*vkp + 1)*HDIM + vd0;

    const uint32_t* mrow_lo = mask + ((size_t)b*SEQ + q0 + gr) * (SEQ/32);
    const uint32_t* mrow_hi = mrow_lo + 8 * (SEQ/32);

    // per-lane ldmatrix base addresses (shared space, buffer 0)
    const uint32_t ks_smem = (uint32_t)__cvta_generic_to_shared(&Ks[0][0]);
    const uint32_t vp_smem = (uint32_t)__cvta_generic_to_shared(&Vp[0][0]);
    const uint32_t ks_lane = ks_smem + (((lane & 7)*KS_STRIDE + (lane >> 3)*4) << 2);
    const uint32_t vp_lane = vp_smem + (((lane & 7)*VP_STRIDE + (lane >> 3)*4) << 2);

    float o[4][4];
    #pragma unroll
    for (int i = 0; i < 4; i++)
        #pragma unroll
        for (int j = 0; j < 4; j++) o[i][j] = 0.f;
    float sum_lo = 0.f, sum_hi = 0.f;

    // prefetch tile 0
    uint4 kv  = *(const uint4*)kgp;
    uint2 vr0 = *(const uint2*)vg0;
    uint2 vr1 = *(const uint2*)vg1;
    uint2 mlo = *(const uint2*)&mrow_lo[0];
    uint2 mhi = *(const uint2*)&mrow_hi[0];

    for (int kt = 0; kt < SEQ/64; kt++) {
        const int buf = kt & 1;

        // store prefetched tile into smem buffer
        *(uint4*)&Ks[buf][kn*KS_STRIDE + kc*4] = kv;
        Vp[buf][(vd0    )*VP_STRIDE + vkp] = __byte_perm(vr0.x, vr1.x, 0x5410);
        Vp[buf][(vd0 + 1)*VP_STRIDE + vkp] = __byte_perm(vr0.x, vr1.x, 0x7632);
        Vp[buf][(vd0 + 2)*VP_STRIDE + vkp] = __byte_perm(vr0.y, vr1.y, 0x5410);
        Vp[buf][(vd0 + 3)*VP_STRIDE + vkp] = __byte_perm(vr0.y, vr1.y, 0x7632);
        const uint2 cm_lo = mlo, cm_hi = mhi;
        __syncthreads();

        // prefetch next tile into registers
        if (kt + 1 < SEQ/64) {
            const int koff = (kt + 1) * 64 * HDIM;
            kv  = *(const uint4*)(kgp + koff);
            vr0 = *(const uint2*)(vg0 + koff);
            vr1 = *(const uint2*)(vg1 + koff);
            mlo = *(const uint2*)&mrow_lo[(kt + 1)*2];
            mhi = *(const uint2*)&mrow_hi[(kt + 1)*2];
        }

        // ---- scores ----
        const uint32_t ksb = ks_lane + buf*(KS_WORDS*4);
        uint32_t P0[8], P1[8];
        #pragma unroll
        for (int nt = 0; nt < 8; nt++) {
            uint32_t kb0, kb1, kb2, kb3;
            ldmx4(kb0, kb1, kb2, kb3, ksb + nt*(8*KS_STRIDE*4));
            float s[4] = {0.f, 0.f, 0.f, 0.f};
            mma16816(s, qa[0], kb0, kb1);
            mma16816(s, qa[1], kb2, kb3);
            const uint32_t wlo = (nt < 4) ? cm_lo.x : cm_lo.y;
            const uint32_t whi = (nt < 4) ? cm_hi.x : cm_hi.y;
            const int sh = ((nt & 3) * 8) + c2;
            const uint32_t ulo = wlo >> sh;
            const uint32_t uhi = whi >> sh;
            const float p0 = (ulo & 1u) ? __expf(s[0]) : 0.f;
            const float p1 = (ulo & 2u) ? __expf(s[1]) : 0.f;
            const float p2 = (uhi & 1u) ? __expf(s[2]) : 0.f;
            const float p3 = (uhi & 2u) ? __expf(s[3]) : 0.f;
            sum_lo += p0 + p1;
            sum_hi += p2 + p3;
            P0[nt] = pack_bf16x2(p0, p1);
            P1[nt] = pack_bf16x2(p2, p3);
        }

        // ---- PV ----
        const uint32_t vpb = vp_lane + buf*(VP_WORDS*4);
        #pragma unroll
        for (int dt = 0; dt < 4; dt++) {
            #pragma unroll
            for (int hf = 0; hf < 2; hf++) {
                uint32_t vb0, vb1, vb2, vb3;
                ldmx4(vb0, vb1, vb2, vb3,
                      vpb + dt*(8*VP_STRIDE*4) + hf*64);
                const int kt2a = 2*hf, kt2b = 2*hf + 1;
                {
                    const uint32_t a[4] = {P0[2*kt2a], P1[2*kt2a],
                                           P0[2*kt2a+1], P1[2*kt2a+1]};
                    mma16816(o[dt], a, vb0, vb1);
                }
                {
                    const uint32_t a[4] = {P0[2*kt2b], P1[2*kt2b],
                                           P0[2*kt2b+1], P1[2*kt2b+1]};
                    mma16816(o[dt], a, vb2, vb3);
                }
            }
        }
    }

    sum_lo += __shfl_xor_sync(0xffffffffu, sum_lo, 1);
    sum_lo += __shfl_xor_sync(0xffffffffu, sum_lo, 2);
    sum_hi += __shfl_xor_sync(0xffffffffu, sum_hi, 1);
    sum_hi += __shfl_xor_sync(0xffffffffu, sum_hi, 2);
    const float inv_lo = 1.f / sum_lo;
    const float inv_hi = 1.f / sum_hi;

    const int n_  = b*NHEAD + h;
    const int bo  = n_ & 3;
    const int hp  = n_ >> 2;
    #pragma unroll
    for (int dt = 0; dt < 4; dt++) {
        const size_t base = ((size_t)(bo*SEQ + q0 + gr))*DIM + hp*HDIM + dt*8 + c2;
        float2 lo, hi;
        lo.x = o[dt][0]*inv_lo; lo.y = o[dt][1]*inv_lo;
        hi.x = o[dt][2]*inv_hi; hi.y = o[dt][3]*inv_hi;
        *(float2*)&outp[base]         = lo;
        *(float2*)&outp[base + 8*DIM] = hi;
    }
}

// ---------------------------------------------------------------------------
extern "C" void kernel_launch(void* const* d_in, const int* in_sizes, int n_in,
                              void* d_out, int out_size)
{
    const float* x     = (const float*)d_in[0];
    const int*   adj   = (const int*)  d_in[1];
    const float* w_qkv = (const float*)d_in[2];
    const float* b_qkv = (const float*)d_in[3];
    const float* ln_g  = (const float*)d_in[4];
    const float* ln_b  = (const float*)d_in[5];
    const float* w_fc  = (const float*)d_in[6];
    const float* b_fc  = (const float*)d_in[7];
    const float* w_z   = (const float*)d_in[8];
    const float* b_z   = (const float*)d_in[9];
    const float* u_z   = (const float*)d_in[10];
    const float* w_r   = (const float*)d_in[11];
    const float* u_r   = (const float*)d_in[12];
    const float* w_g   = (const float*)d_in[13];
    const float* u_g   = (const float*)d_in[14];
    float* out = (float*)d_out;

    float *xn, *att, *y, *z, *rx;
    __nv_bfloat16 *qb, *kb, *vb;
    uint32_t *mask;
    cudaGetSymbolAddress((void**)&xn,   g_xn);
    cudaGetSymbolAddress((void**)&att,  g_att);
    cudaGetSymbolAddress((void**)&y,    g_y);
    cudaGetSymbolAddress((void**)&z,    g_z);
    cudaGetSymbolAddress((void**)&rx,   g_rx);
    cudaGetSymbolAddress((void**)&qb,   g_q);
    cudaGetSymbolAddress((void**)&kb,   g_k);
    cudaGetSymbolAddress((void**)&vb,   g_v);
    cudaGetSymbolAddress((void**)&mask, g_mask);

    // 0. pack adjacency into bitmask
    pack_adj<<<BATCH*SEQ*SEQ/256, 256>>>(adj, mask);
    // 1. LayerNorm
    ln_kernel<<<M_TOT, 256>>>(x, ln_g, ln_b, xn);
    // 2. QKV projection (tf32 TC) -> bf16 q/k/v per-head buffers
    gemm_tc<<<dim3(12, 64), 256>>>(xn, nullptr, w_qkv, nullptr, nullptr, nullptr,
                                   b_qkv, nullptr, nullptr,
                                   nullptr, nullptr, qb, kb, vb, MODE_QKV, 8);
    // 3. bf16 tensor-core flash attention
    attn_mma<<<dim3(SEQ/128, NHEAD, BATCH), 256>>>(qb, kb, vb, mask, att);
    // 4. FC + ReLU (tf32 TC)
    gemm_tc<<<dim3(4, 64), 256>>>(att, nullptr, w_fc, nullptr, nullptr, nullptr,
                                  b_fc, nullptr, nullptr,
                                  y, nullptr, nullptr, nullptr, nullptr, MODE_FC, 8);
    // 5. fused ZR: z = sigmoid(y@w_z^T+b_z+x@u_z^T); rx = sigmoid(y@w_r^T+x@u_r^T)*x
    gemm_tc<<<dim3(8, 64), 256>>>(y, x, w_z, u_z, w_r, u_r,
                                  b_z, x, nullptr,
                                  z, rx, nullptr, nullptr, nullptr, MODE_ZR, 16);
    // 6. H: out = (1-z)*x + z*tanh(y@w_g^T + rx@u_g^T)
    gemm_tc<<<dim3(4, 64), 256>>>(y, rx, w_g, u_g, nullptr, nullptr,
                                  nullptr, x, z,
                                  out, nullptr, nullptr, nullptr, nullptr, MODE_H, 16);
}

// round 5
// speedup vs baseline: 4.3708x; 1.1123x over previous
#include <cuda_runtime.h>
#include <cuda_bf16.h>
#include <cuda_fp16.h>
#include <cstdint>

// Problem constants
#define SEQ   2048
#define BATCH 4
#define DIM   256
#define NHEAD 8
#define HDIM  32
#define M_TOT 8192          // BATCH*SEQ
#define QK_SCALE 0.17677669529663687f            // 1/sqrt(32)
#define Q_PRESCALE (QK_SCALE * 1.4426950408889634f)  // * log2(e): scores in log2 domain

// Scratch (device globals: allocation-free rule)
__device__ float g_xn [M_TOT*DIM];
__device__ float g_att[M_TOT*DIM];
__device__ float g_y  [M_TOT*DIM];
__device__ float g_z  [M_TOT*DIM];
__device__ float g_rx [M_TOT*DIM];
__device__ __nv_bfloat16 g_q[M_TOT*HDIM*NHEAD];   // [B*H, S, 32]
__device__ __nv_bfloat16 g_k[M_TOT*HDIM*NHEAD];
__device__ __half        g_v[M_TOT*HDIM*NHEAD];   // fp16 V
__device__ uint32_t g_mask[BATCH*SEQ*(SEQ/32)];   // 2MB bit mask

// ---------------------------------------------------------------------------
__global__ void pack_adj(const int* __restrict__ adj, uint32_t* __restrict__ mask)
{
    const int idx = blockIdx.x * 256 + threadIdx.x;
    const int v = adj[idx];
    const uint32_t bal = __ballot_sync(0xffffffffu, v != 0);
    if ((threadIdx.x & 31) == 0) mask[idx >> 5] = bal;
}

// ---------------------------------------------------------------------------
__global__ void ln_kernel(const float* __restrict__ x,
                          const float* __restrict__ gamma,
                          const float* __restrict__ beta,
                          float* __restrict__ out)
{
    const int row = blockIdx.x;
    const int tid = threadIdx.x;
    const float v = x[(size_t)row*DIM + tid];
    float s = v, s2 = v*v;
    #pragma unroll
    for (int o = 16; o; o >>= 1) {
        s  += __shfl_xor_sync(0xffffffffu, s,  o);
        s2 += __shfl_xor_sync(0xffffffffu, s2, o);
    }
    __shared__ float ps[8], ps2[8];
    if ((tid & 31) == 0) { ps[tid>>5] = s; ps2[tid>>5] = s2; }
    __syncthreads();
    float tot = 0.f, tot2 = 0.f;
    #pragma unroll
    for (int i = 0; i < 8; i++) { tot += ps[i]; tot2 += ps2[i]; }
    const float mu   = tot * (1.0f/DIM);
    const float var  = tot2 * (1.0f/DIM) - mu*mu;
    const float rstd = rsqrtf(var + 1e-5f);
    out[(size_t)row*DIM + tid] = (v - mu) * rstd * gamma[tid] + beta[tid];
}

// ---------------------------------------------------------------------------
// helpers
// ---------------------------------------------------------------------------
__device__ __forceinline__ uint32_t f2tf32(float f)
{
    uint32_t r;
    asm("cvt.rna.tf32.f32 %0, %1;" : "=r"(r) : "f"(f));
    return r;
}

__device__ __forceinline__ void mma_tf32(float* d, const uint32_t* a,
                                         uint32_t b0, uint32_t b1)
{
    asm volatile("mma.sync.aligned.m16n8k8.row.col.f32.tf32.tf32.f32 "
                 "{%0,%1,%2,%3},{%4,%5,%6,%7},{%8,%9},{%0,%1,%2,%3};\n"
                 : "+f"(d[0]), "+f"(d[1]), "+f"(d[2]), "+f"(d[3])
                 : "r"(a[0]), "r"(a[1]), "r"(a[2]), "r"(a[3]),
                   "r"(b0), "r"(b1));
}

__device__ __forceinline__ uint32_t pack_bf16x2(float lo, float hi)
{
    uint32_t r;
    asm("cvt.rn.bf16x2.f32 %0, %1, %2;" : "=r"(r) : "f"(hi), "f"(lo));
    return r;
}

__device__ __forceinline__ uint32_t pack_f16x2(float lo, float hi)
{
    uint32_t r;
    asm("cvt.rn.f16x2.f32 %0, %1, %2;" : "=r"(r) : "f"(hi), "f"(lo));
    return r;
}

__device__ __forceinline__ uint32_t ex2_f16x2(uint32_t x)
{
    uint32_t r;
    asm("ex2.approx.f16x2 %0, %1;" : "=r"(r) : "r"(x));
    return r;
}

__device__ __forceinline__ void ldmx4(uint32_t& r0, uint32_t& r1,
                                      uint32_t& r2, uint32_t& r3, uint32_t addr)
{
    asm volatile("ldmatrix.sync.aligned.m8n8.x4.shared.b16 {%0,%1,%2,%3},[%4];"
                 : "=r"(r0), "=r"(r1), "=r"(r2), "=r"(r3) : "r"(addr));
}

// ---------------------------------------------------------------------------
// tf32 tensor-core GEMM; fragment loads via ldmatrix.x4 (tf32-as-b16 trick).
// ---------------------------------------------------------------------------
enum { MODE_QKV = 0, MODE_FC = 1, MODE_ZR = 2, MODE_H = 3 };

#define AST 36

__global__ void __launch_bounds__(256)
gemm_tc(const float* __restrict__ A1, const float* __restrict__ A2,
        const float* __restrict__ B00, const float* __restrict__ B01,
        const float* __restrict__ B10, const float* __restrict__ B11,
        const float* __restrict__ bias,
        const float* __restrict__ X,
        const float* __restrict__ Zb,
        float* __restrict__ C,
        float* __restrict__ Crx,
        __nv_bfloat16* __restrict__ qb,
        __nv_bfloat16* __restrict__ kb,
        __half* __restrict__ vb,
        int mode, int KT)
{
    __shared__ uint32_t As[128*AST];
    __shared__ uint32_t Bs[64*AST];

    const int tid  = threadIdx.x;
    const int lane = tid & 31;
    const int w    = tid >> 5;
    const int wm   = w >> 1, wn = w & 1;
    const int m0   = blockIdx.y * 128;
    const int n0   = blockIdx.x * 64;
    const int half = (mode == MODE_ZR && n0 >= 256) ? 1 : 0;
    const int brow0 = n0 - (half ? 256 : 0);

    // ldmatrix lane addresses
    const uint32_t as_base = (uint32_t)__cvta_generic_to_shared(As);
    const uint32_t bs_base = (uint32_t)__cvta_generic_to_shared(Bs);
    const uint32_t a_addr = as_base +
        (((wm*32 + (lane & 15))*AST + (lane >> 4)*4) << 2);
    const uint32_t b_addr = bs_base +
        (((wn*32 + (lane & 7) + (lane >> 4)*8)*AST + ((lane >> 3) & 1)*4) << 2);

    float acc[8][4];
    #pragma unroll
    for (int i = 0; i < 8; i++)
        #pragma unroll
        for (int j = 0; j < 4; j++) acc[i][j] = 0.f;

    float4 pa[4], pb[2];
    {
        const float* Ap = A1;
        const float* Bp = half ? B10 : B00;
        #pragma unroll
        for (int it = 0; it < 4; it++) {
            const int lin = tid + it*256, r = lin >> 3, cq = (lin & 7) * 4;
            pa[it] = *(const float4*)&Ap[(size_t)(m0 + r)*256 + cq];
        }
        #pragma unroll
        for (int it = 0; it < 2; it++) {
            const int lin = tid + it*256, r = lin >> 3, cq = (lin & 7) * 4;
            pb[it] = *(const float4*)&Bp[(size_t)(brow0 + r)*256 + cq];
        }
    }

    for (int kt = 0; kt < KT; kt++) {
        #pragma unroll
        for (int it = 0; it < 4; it++) {
            const int lin = tid + it*256, r = lin >> 3, cq = (lin & 7) * 4;
            uint32_t* d = &As[r*AST + cq];
            d[0] = f2tf32(pa[it].x); d[1] = f2tf32(pa[it].y);
            d[2] = f2tf32(pa[it].z); d[3] = f2tf32(pa[it].w);
        }
        #pragma unroll
        for (int it = 0; it < 2; it++) {
            const int lin = tid + it*256, r = lin >> 3, cq = (lin & 7) * 4;
            uint32_t* d = &Bs[r*AST + cq];
            d[0] = f2tf32(pb[it].x); d[1] = f2tf32(pb[it].y);
            d[2] = f2tf32(pb[it].z); d[3] = f2tf32(pb[it].w);
        }
        __syncthreads();

        if (kt + 1 < KT) {
            const int kg    = (kt + 1) * 32;
            const int phase = kg >= 256;
            const int k0    = kg & 255;
            const float* Ap = phase ? A2 : A1;
            const float* Bp = half ? (phase ? B11 : B10) : (phase ? B01 : B00);
            #pragma unroll
            for (int it = 0; it < 4; it++) {
                const int lin = tid + it*256, r = lin >> 3, cq = (lin & 7) * 4;
                pa[it] = *(const float4*)&Ap[(size_t)(m0 + r)*256 + k0 + cq];
            }
            #pragma unroll
            for (int it = 0; it < 2; it++) {
                const int lin = tid + it*256, r = lin >> 3, cq = (lin & 7) * 4;
                pb[it] = *(const float4*)&Bp[(size_t)(brow0 + r)*256 + k0 + cq];
            }
        }

        #pragma unroll
        for (int k8 = 0; k8 < 4; k8++) {
            const uint32_t koff = k8 * 32;   // 8 words
            uint32_t a0[4], a1[4], bA[4], bB[4];
            ldmx4(a0[0], a0[1], a0[2], a0[3], a_addr + koff);
            ldmx4(a1[0], a1[1], a1[2], a1[3], a_addr + 16*AST*4 + koff);
            ldmx4(bA[0], bA[1], bA[2], bA[3], b_addr + koff);
            ldmx4(bB[0], bB[1], bB[2], bB[3], b_addr + 16*AST*4 + koff);
            mma_tf32(acc[0], a0, bA[0], bA[1]);
            mma_tf32(acc[1], a0, bA[2], bA[3]);
            mma_tf32(acc[2], a0, bB[0], bB[1]);
            mma_tf32(acc[3], a0, bB[2], bB[3]);
            mma_tf32(acc[4], a1, bA[0], bA[1]);
            mma_tf32(acc[5], a1, bA[2], bA[3]);
            mma_tf32(acc[6], a1, bB[0], bB[1]);
            mma_tf32(acc[7], a1, bB[2], bB[3]);
        }
        __syncthreads();
    }

    const int rbase = m0 + wm*32 + (lane >> 2);
    const int cbase = n0 + wn*32 + 2*(lane & 3);

    #pragma unroll
    for (int tm = 0; tm < 2; tm++) {
        #pragma unroll
        for (int tn = 0; tn < 4; tn++) {
            const float* ac = acc[tm*4 + tn];
            const int c = cbase + tn*8;
            #pragma unroll
            for (int hrow = 0; hrow < 2; hrow++) {
                const int m = rbase + tm*16 + hrow*8;
                const float v0 = ac[hrow*2], v1 = ac[hrow*2 + 1];
                if (mode == MODE_QKV) {
                    const int b_ = m >> 11, s_ = m & 2047;
                    const int h_ = c / 96, buf = (c >> 5) % 3, d_ = c & 31;
                    const size_t dst = ((size_t)((b_*NHEAD + h_)*SEQ + s_))*HDIM + d_;
                    if (buf == 2) {
                        // V: fp16
                        *(uint32_t*)&vb[dst] = pack_f16x2(v0 + bias[c], v1 + bias[c+1]);
                    } else {
                        const float sc = (buf == 0) ? Q_PRESCALE : 1.0f;
                        const uint32_t pk = pack_bf16x2((v0 + bias[c])*sc,
                                                        (v1 + bias[c+1])*sc);
                        __nv_bfloat16* base = (buf == 0) ? qb : kb;
                        *(uint32_t*)&base[dst] = pk;
                    }
                } else if (mode == MODE_FC) {
                    float2 o;
                    o.x = fmaxf(v0 + bias[c],   0.f);
                    o.y = fmaxf(v1 + bias[c+1], 0.f);
                    *(float2*)&C[(size_t)m*256 + c] = o;
                } else if (mode == MODE_ZR) {
                    if (!half) {
                        float2 o;
                        o.x = 1.f/(1.f + __expf(-(v0 + bias[c])));
                        o.y = 1.f/(1.f + __expf(-(v1 + bias[c+1])));
                        *(float2*)&C[(size_t)m*256 + c] = o;
                    } else {
                        const int nc = c - 256;
                        const float2 xv = *(const float2*)&X[(size_t)m*256 + nc];
                        float2 o;
                        o.x = xv.x / (1.f + __expf(-v0));
                        o.y = xv.y / (1.f + __expf(-v1));
                        *(float2*)&Crx[(size_t)m*256 + nc] = o;
                    }
                } else {
                    const float2 zz = *(const float2*)&Zb[(size_t)m*256 + c];
                    const float2 xv = *(const float2*)&X [(size_t)m*256 + c];
                    float2 o;
                    o.x = (1.f - zz.x)*xv.x + zz.x*tanhf(v0);
                    o.y = (1.f - zz.y)*xv.y + zz.y*tanhf(v1);
                    *(float2*)&C[(size_t)m*256 + c] = o;
                }
            }
        }
    }
}

// ---------------------------------------------------------------------------
// flash attention v3:
//  - scores bf16 mma (Q pre-scaled into log2 domain)
//  - packed fp16 exp: cvt.f16x2 + ex2.approx.f16x2 (half the MUFU ops)
//  - mask applied by integer AND with IMAD-built maskword
//  - row sums via ones-column fp16 MMA (no scalar fadds; denominator uses
//    the exact same fp16 P as the numerator)
//  - PV in fp16, double-buffered tiles, ldmatrix fragments
// ---------------------------------------------------------------------------
__device__ __forceinline__ void mma16816bf(float* d, const uint32_t* a,
                                           uint32_t b0, uint32_t b1)
{
    asm volatile("mma.sync.aligned.m16n8k16.row.col.f32.bf16.bf16.f32 "
                 "{%0,%1,%2,%3},{%4,%5,%6,%7},{%8,%9},{%0,%1,%2,%3};\n"
                 : "+f"(d[0]), "+f"(d[1]), "+f"(d[2]), "+f"(d[3])
                 : "r"(a[0]), "r"(a[1]), "r"(a[2]), "r"(a[3]),
                   "r"(b0), "r"(b1));
}

__device__ __forceinline__ void mma16816h(float* d, const uint32_t* a,
                                          uint32_t b0, uint32_t b1)
{
    asm volatile("mma.sync.aligned.m16n8k16.row.col.f32.f16.f16.f32 "
                 "{%0,%1,%2,%3},{%4,%5,%6,%7},{%8,%9},{%0,%1,%2,%3};\n"
                 : "+f"(d[0]), "+f"(d[1]), "+f"(d[2]), "+f"(d[3])
                 : "r"(a[0]), "r"(a[1]), "r"(a[2]), "r"(a[3]),
                   "r"(b0), "r"(b1));
}

#define KS_STRIDE 36
#define VP_STRIDE 36
#define KS_WORDS  (64*KS_STRIDE)
#define VP_WORDS  (32*VP_STRIDE)

__global__ void __launch_bounds__(256, 2)
attn_mma(const __nv_bfloat16* __restrict__ q,
         const __nv_bfloat16* __restrict__ k,
         const __half* __restrict__ v,
         const uint32_t* __restrict__ mask,
         float* __restrict__ outp)
{
    const int tid  = threadIdx.x;
    const int lane = tid & 31;
    const int w    = tid >> 5;
    const int h    = blockIdx.y;
    const int b    = blockIdx.z;
    const int q0   = blockIdx.x * 128;

    const size_t nb = (size_t)(b*NHEAD + h) * SEQ;
    const int gr = w*16 + (lane >> 2);
    const int c2 = (lane & 3) * 2;

    __shared__ uint32_t Ks[2][KS_WORDS];
    __shared__ uint32_t Vp[2][VP_WORDS];

    uint32_t qa[2][4];
    {
        const __nv_bfloat16* qbase = q + (nb + q0) * HDIM;
        #pragma unroll
        for (int kt = 0; kt < 2; kt++) {
            qa[kt][0] = *(const uint32_t*)&qbase[(size_t)(gr    )*HDIM + kt*16 + c2    ];
            qa[kt][1] = *(const uint32_t*)&qbase[(size_t)(gr + 8)*HDIM + kt*16 + c2    ];
            qa[kt][2] = *(const uint32_t*)&qbase[(size_t)(gr    )*HDIM + kt*16 + c2 + 8];
            qa[kt][3] = *(const uint32_t*)&qbase[(size_t)(gr + 8)*HDIM + kt*16 + c2 + 8];
        }
    }

    const int kn  = tid >> 2, kc  = tid & 3;
    const int vkp = tid >> 3, vd0 = (tid & 7) * 4;
    const __nv_bfloat16* kgp = k + (nb + kn   )*HDIM + kc*8;
    const __half*        vg0 = v + (nb + 2*vkp    )*HDIM + vd0;
    const __half*        vg1 = v + (nb + 2*vkp + 1)*HDIM + vd0;

    const uint32_t* mrow_lo = mask + ((size_t)b*SEQ + q0 + gr) * (SEQ/32);
    const uint32_t* mrow_hi = mrow_lo + 8 * (SEQ/32);

    const uint32_t ks_smem = (uint32_t)__cvta_generic_to_shared(&Ks[0][0]);
    const uint32_t vp_smem = (uint32_t)__cvta_generic_to_shared(&Vp[0][0]);
    const uint32_t ks_lane = ks_smem + (((lane & 7)*KS_STRIDE + (lane >> 3)*4) << 2);
    const uint32_t vp_lane = vp_smem + (((lane & 7)*VP_STRIDE + (lane >> 3)*4) << 2);

    // ones fragment (fp16 1.0 in column 0 only)
    const uint32_t ones = ((lane >> 2) == 0) ? 0x3C003C00u : 0u;

    float o[4][4];
    #pragma unroll
    for (int i = 0; i < 4; i++)
        #pragma unroll
        for (int j = 0; j < 4; j++) o[i][j] = 0.f;
    float o4[4] = {0.f, 0.f, 0.f, 0.f};   // row-sum accumulator (col 0)

    uint4 kv  = *(const uint4*)kgp;
    uint2 vr0 = *(const uint2*)vg0;
    uint2 vr1 = *(const uint2*)vg1;
    uint2 mlo = *(const uint2*)&mrow_lo[0];
    uint2 mhi = *(const uint2*)&mrow_hi[0];

    for (int kt = 0; kt < SEQ/64; kt++) {
        const int buf = kt & 1;

        *(uint4*)&Ks[buf][kn*KS_STRIDE + kc*4] = kv;
        Vp[buf][(vd0    )*VP_STRIDE + vkp] = __byte_perm(vr0.x, vr1.x, 0x5410);
        Vp[buf][(vd0 + 1)*VP_STRIDE + vkp] = __byte_perm(vr0.x, vr1.x, 0x7632);
        Vp[buf][(vd0 + 2)*VP_STRIDE + vkp] = __byte_perm(vr0.y, vr1.y, 0x5410);
        Vp[buf][(vd0 + 3)*VP_STRIDE + vkp] = __byte_perm(vr0.y, vr1.y, 0x7632);
        const uint2 cm_lo = mlo, cm_hi = mhi;
        __syncthreads();

        if (kt + 1 < SEQ/64) {
            const int koff = (kt + 1) * 64 * HDIM;
            kv  = *(const uint4*)(kgp + koff);
            vr0 = *(const uint2*)(vg0 + koff);
            vr1 = *(const uint2*)(vg1 + koff);
            mlo = *(const uint2*)&mrow_lo[(kt + 1)*2];
            mhi = *(const uint2*)&mrow_hi[(kt + 1)*2];
        }

        // ---- scores + packed exp + mask ----
        const uint32_t ksb = ks_lane + buf*(KS_WORDS*4);
        uint32_t P0[8], P1[8];
        #pragma unroll
        for (int nt = 0; nt < 8; nt++) {
            uint32_t kb0, kb1, kb2, kb3;
            ldmx4(kb0, kb1, kb2, kb3, ksb + nt*(8*KS_STRIDE*4));
            float s[4] = {0.f, 0.f, 0.f, 0.f};
            mma16816bf(s, qa[0], kb0, kb1);
            mma16816bf(s, qa[1], kb2, kb3);
            const uint32_t wlo = (nt < 4) ? cm_lo.x : cm_lo.y;
            const uint32_t whi = (nt < 4) ? cm_hi.x : cm_hi.y;
            const int sh = ((nt & 3) * 8) + c2;
            const uint32_t ulo = wlo >> sh;
            const uint32_t uhi = whi >> sh;
            const uint32_t mwlo = (ulo & 1u)*0xFFFFu + (ulo & 2u)*0x7FFF8000u;
            const uint32_t mwhi = (uhi & 1u)*0xFFFFu + (uhi & 2u)*0x7FFF8000u;
            P0[nt] = ex2_f16x2(pack_f16x2(s[0], s[1])) & mwlo;
            P1[nt] = ex2_f16x2(pack_f16x2(s[2], s[3])) & mwhi;
        }

        // ---- PV (fp16) + ones-column row sums ----
        const uint32_t vpb = vp_lane + buf*(VP_WORDS*4);
        #pragma unroll
        for (int hf = 0; hf < 2; hf++) {
            const int kt2a = 2*hf, kt2b = 2*hf + 1;
            const uint32_t aA[4] = {P0[2*kt2a], P1[2*kt2a], P0[2*kt2a+1], P1[2*kt2a+1]};
            const uint32_t aB[4] = {P0[2*kt2b], P1[2*kt2b], P0[2*kt2b+1], P1[2*kt2b+1]};
            mma16816h(o4, aA, ones, ones);
            mma16816h(o4, aB, ones, ones);
            #pragma unroll
            for (int dt = 0; dt < 4; dt++) {
                uint32_t vb0, vb1, vb2, vb3;
                ldmx4(vb0, vb1, vb2, vb3, vpb + dt*(8*VP_STRIDE*4) + hf*64);
                mma16816h(o[dt], aA, vb0, vb1);
                mma16816h(o[dt], aB, vb2, vb3);
            }
        }
    }

    // row sums live in col 0 of o4 (lanes with lane&3==0)
    const float sum_lo = __shfl_sync(0xffffffffu, o4[0], lane & ~3);
    const float sum_hi = __shfl_sync(0xffffffffu, o4[2], lane & ~3);
    const float inv_lo = 1.f / sum_lo;
    const float inv_hi = 1.f / sum_hi;

    const int n_  = b*NHEAD + h;
    const int bo  = n_ & 3;
    const int hp  = n_ >> 2;
    #pragma unroll
    for (int dt = 0; dt < 4; dt++) {
        const size_t base = ((size_t)(bo*SEQ + q0 + gr))*DIM + hp*HDIM + dt*8 + c2;
        float2 lo, hi;
        lo.x = o[dt][0]*inv_lo; lo.y = o[dt][1]*inv_lo;
        hi.x = o[dt][2]*inv_hi; hi.y = o[dt][3]*inv_hi;
        *(float2*)&outp[base]         = lo;
        *(float2*)&outp[base + 8*DIM] = hi;
    }
}

// ---------------------------------------------------------------------------
extern "C" void kernel_launch(void* const* d_in, const int* in_sizes, int n_in,
                              void* d_out, int out_size)
{
    const float* x     = (const float*)d_in[0];
    const int*   adj   = (const int*)  d_in[1];
    const float* w_qkv = (const float*)d_in[2];
    const float* b_qkv = (const float*)d_in[3];
    const float* ln_g  = (const float*)d_in[4];
    const float* ln_b  = (const float*)d_in[5];
    const float* w_fc  = (const float*)d_in[6];
    const float* b_fc  = (const float*)d_in[7];
    const float* w_z   = (const float*)d_in[8];
    const float* b_z   = (const float*)d_in[9];
    const float* u_z   = (const float*)d_in[10];
    const float* w_r   = (const float*)d_in[11];
    const float* u_r   = (const float*)d_in[12];
    const float* w_g   = (const float*)d_in[13];
    const float* u_g   = (const float*)d_in[14];
    float* out = (float*)d_out;

    float *xn, *att, *y, *z, *rx;
    __nv_bfloat16 *qb, *kb;
    __half *vb;
    uint32_t *mask;
    cudaGetSymbolAddress((void**)&xn,   g_xn);
    cudaGetSymbolAddress((void**)&att,  g_att);
    cudaGetSymbolAddress((void**)&y,    g_y);
    cudaGetSymbolAddress((void**)&z,    g_z);
    cudaGetSymbolAddress((void**)&rx,   g_rx);
    cudaGetSymbolAddress((void**)&qb,   g_q);
    cudaGetSymbolAddress((void**)&kb,   g_k);
    cudaGetSymbolAddress((void**)&vb,   g_v);
    cudaGetSymbolAddress((void**)&mask, g_mask);

    // 0. pack adjacency into bitmask
    pack_adj<<<BATCH*SEQ*SEQ/256, 256>>>(adj, mask);
    // 1. LayerNorm
    ln_kernel<<<M_TOT, 256>>>(x, ln_g, ln_b, xn);
    // 2. QKV projection (tf32 TC) -> q (bf16, log2-prescaled), k (bf16), v (fp16)
    gemm_tc<<<dim3(12, 64), 256>>>(xn, nullptr, w_qkv, nullptr, nullptr, nullptr,
                                   b_qkv, nullptr, nullptr,
                                   nullptr, nullptr, qb, kb, vb, MODE_QKV, 8);
    // 3. flash attention (bf16 QK, fp16 PV, ex2.f16x2 softmax)
    attn_mma<<<dim3(SEQ/128, NHEAD, BATCH), 256>>>(qb, kb, vb, mask, att);
    // 4. FC + ReLU
    gemm_tc<<<dim3(4, 64), 256>>>(att, nullptr, w_fc, nullptr, nullptr, nullptr,
                                  b_fc, nullptr, nullptr,
                                  y, nullptr, nullptr, nullptr, nullptr, MODE_FC, 8);
    // 5. fused ZR: z = sigmoid(y@w_z^T+b_z+x@u_z^T); rx = sigmoid(y@w_r^T+x@u_r^T)*x
    gemm_tc<<<dim3(8, 64), 256>>>(y, x, w_z, u_z, w_r, u_r,
                                  b_z, x, nullptr,
                                  z, rx, nullptr, nullptr, nullptr, MODE_ZR, 16);
    // 6. H: out = (1-z)*x + z*tanh(y@w_g^T + rx@u_g^T)
    gemm_tc<<<dim3(4, 64), 256>>>(y, rx, w_g, u_g, nullptr, nullptr,
                                  nullptr, x, z,
                                  out, nullptr, nullptr, nullptr, nullptr, MODE_H, 16);
}

// round 6
// speedup vs baseline: 4.4351x; 1.0147x over previous
#include <cuda_runtime.h>
#include <cuda_bf16.h>
#include <cuda_fp16.h>
#include <cstdint>

// Problem constants
#define SEQ   2048
#define BATCH 4
#define DIM   256
#define NHEAD 8
#define HDIM  32
#define M_TOT 8192          // BATCH*SEQ
#define QK_SCALE 0.17677669529663687f            // 1/sqrt(32)
#define Q_PRESCALE (QK_SCALE * 1.4426950408889634f)  // * log2(e): scores in log2 domain

// Scratch (device globals: allocation-free rule)
__device__ float g_xn [M_TOT*DIM];
__device__ float g_att[M_TOT*DIM];
__device__ float g_y  [M_TOT*DIM];
__device__ float g_z  [M_TOT*DIM];
__device__ float g_rx [M_TOT*DIM];
__device__ __nv_bfloat16 g_q[M_TOT*HDIM*NHEAD];   // [B*H, S, 32]
__device__ __nv_bfloat16 g_k[M_TOT*HDIM*NHEAD];
__device__ __half        g_v[M_TOT*HDIM*NHEAD];   // fp16 V
__device__ uint32_t g_mask[BATCH*SEQ*(SEQ/32)];   // 2MB bit mask

// ---------------------------------------------------------------------------
__global__ void pack_adj(const int* __restrict__ adj, uint32_t* __restrict__ mask)
{
    const int idx = blockIdx.x * 256 + threadIdx.x;
    const int v = adj[idx];
    const uint32_t bal = __ballot_sync(0xffffffffu, v != 0);
    if ((threadIdx.x & 31) == 0) mask[idx >> 5] = bal;
}

// ---------------------------------------------------------------------------
__global__ void ln_kernel(const float* __restrict__ x,
                          const float* __restrict__ gamma,
                          const float* __restrict__ beta,
                          float* __restrict__ out)
{
    const int row = blockIdx.x;
    const int tid = threadIdx.x;
    const float v = x[(size_t)row*DIM + tid];
    float s = v, s2 = v*v;
    #pragma unroll
    for (int o = 16; o; o >>= 1) {
        s  += __shfl_xor_sync(0xffffffffu, s,  o);
        s2 += __shfl_xor_sync(0xffffffffu, s2, o);
    }
    __shared__ float ps[8], ps2[8];
    if ((tid & 31) == 0) { ps[tid>>5] = s; ps2[tid>>5] = s2; }
    __syncthreads();
    float tot = 0.f, tot2 = 0.f;
    #pragma unroll
    for (int i = 0; i < 8; i++) { tot += ps[i]; tot2 += ps2[i]; }
    const float mu   = tot * (1.0f/DIM);
    const float var  = tot2 * (1.0f/DIM) - mu*mu;
    const float rstd = rsqrtf(var + 1e-5f);
    out[(size_t)row*DIM + tid] = (v - mu) * rstd * gamma[tid] + beta[tid];
}

// ---------------------------------------------------------------------------
// helpers
// ---------------------------------------------------------------------------
__device__ __forceinline__ uint32_t f2tf32(float f)
{
    uint32_t r;
    asm("cvt.rna.tf32.f32 %0, %1;" : "=r"(r) : "f"(f));
    return r;
}

__device__ __forceinline__ void mma_tf32(float* d, const uint32_t* a,
                                         uint32_t b0, uint32_t b1)
{
    asm volatile("mma.sync.aligned.m16n8k8.row.col.f32.tf32.tf32.f32 "
                 "{%0,%1,%2,%3},{%4,%5,%6,%7},{%8,%9},{%0,%1,%2,%3};\n"
                 : "+f"(d[0]), "+f"(d[1]), "+f"(d[2]), "+f"(d[3])
                 : "r"(a[0]), "r"(a[1]), "r"(a[2]), "r"(a[3]),
                   "r"(b0), "r"(b1));
}

__device__ __forceinline__ uint32_t pack_bf16x2(float lo, float hi)
{
    uint32_t r;
    asm("cvt.rn.bf16x2.f32 %0, %1, %2;" : "=r"(r) : "f"(hi), "f"(lo));
    return r;
}

__device__ __forceinline__ uint32_t pack_f16x2(float lo, float hi)
{
    uint32_t r;
    asm("cvt.rn.f16x2.f32 %0, %1, %2;" : "=r"(r) : "f"(hi), "f"(lo));
    return r;
}

__device__ __forceinline__ uint32_t ex2_f16x2(uint32_t x)
{
    uint32_t r;
    asm("ex2.approx.f16x2 %0, %1;" : "=r"(r) : "r"(x));
    return r;
}

__device__ __forceinline__ void ldmx4(uint32_t& r0, uint32_t& r1,
                                      uint32_t& r2, uint32_t& r3, uint32_t addr)
{
    asm volatile("ldmatrix.sync.aligned.m8n8.x4.shared.b16 {%0,%1,%2,%3},[%4];"
                 : "=r"(r0), "=r"(r1), "=r"(r2), "=r"(r3) : "r"(addr));
}

// ---------------------------------------------------------------------------
// tf32 tensor-core GEMM (unchanged from round 5).
// ---------------------------------------------------------------------------
enum { MODE_QKV = 0, MODE_FC = 1, MODE_ZR = 2, MODE_H = 3 };

#define AST 36

__global__ void __launch_bounds__(256)
gemm_tc(const float* __restrict__ A1, const float* __restrict__ A2,
        const float* __restrict__ B00, const float* __restrict__ B01,
        const float* __restrict__ B10, const float* __restrict__ B11,
        const float* __restrict__ bias,
        const float* __restrict__ X,
        const float* __restrict__ Zb,
        float* __restrict__ C,
        float* __restrict__ Crx,
        __nv_bfloat16* __restrict__ qb,
        __nv_bfloat16* __restrict__ kb,
        __half* __restrict__ vb,
        int mode, int KT)
{
    __shared__ uint32_t As[128*AST];
    __shared__ uint32_t Bs[64*AST];

    const int tid  = threadIdx.x;
    const int lane = tid & 31;
    const int w    = tid >> 5;
    const int wm   = w >> 1, wn = w & 1;
    const int m0   = blockIdx.y * 128;
    const int n0   = blockIdx.x * 64;
    const int half = (mode == MODE_ZR && n0 >= 256) ? 1 : 0;
    const int brow0 = n0 - (half ? 256 : 0);

    const uint32_t as_base = (uint32_t)__cvta_generic_to_shared(As);
    const uint32_t bs_base = (uint32_t)__cvta_generic_to_shared(Bs);
    const uint32_t a_addr = as_base +
        (((wm*32 + (lane & 15))*AST + (lane >> 4)*4) << 2);
    const uint32_t b_addr = bs_base +
        (((wn*32 + (lane & 7) + (lane >> 4)*8)*AST + ((lane >> 3) & 1)*4) << 2);

    float acc[8][4];
    #pragma unroll
    for (int i = 0; i < 8; i++)
        #pragma unroll
        for (int j = 0; j < 4; j++) acc[i][j] = 0.f;

    float4 pa[4], pb[2];
    {
        const float* Ap = A1;
        const float* Bp = half ? B10 : B00;
        #pragma unroll
        for (int it = 0; it < 4; it++) {
            const int lin = tid + it*256, r = lin >> 3, cq = (lin & 7) * 4;
            pa[it] = *(const float4*)&Ap[(size_t)(m0 + r)*256 + cq];
        }
        #pragma unroll
        for (int it = 0; it < 2; it++) {
            const int lin = tid + it*256, r = lin >> 3, cq = (lin & 7) * 4;
            pb[it] = *(const float4*)&Bp[(size_t)(brow0 + r)*256 + cq];
        }
    }

    for (int kt = 0; kt < KT; kt++) {
        #pragma unroll
        for (int it = 0; it < 4; it++) {
            const int lin = tid + it*256, r = lin >> 3, cq = (lin & 7) * 4;
            uint32_t* d = &As[r*AST + cq];
            d[0] = f2tf32(pa[it].x); d[1] = f2tf32(pa[it].y);
            d[2] = f2tf32(pa[it].z); d[3] = f2tf32(pa[it].w);
        }
        #pragma unroll
        for (int it = 0; it < 2; it++) {
            const int lin = tid + it*256, r = lin >> 3, cq = (lin & 7) * 4;
            uint32_t* d = &Bs[r*AST + cq];
            d[0] = f2tf32(pb[it].x); d[1] = f2tf32(pb[it].y);
            d[2] = f2tf32(pb[it].z); d[3] = f2tf32(pb[it].w);
        }
        __syncthreads();

        if (kt + 1 < KT) {
            const int kg    = (kt + 1) * 32;
            const int phase = kg >= 256;
            const int k0    = kg & 255;
            const float* Ap = phase ? A2 : A1;
            const float* Bp = half ? (phase ? B11 : B10) : (phase ? B01 : B00);
            #pragma unroll
            for (int it = 0; it < 4; it++) {
                const int lin = tid + it*256, r = lin >> 3, cq = (lin & 7) * 4;
                pa[it] = *(const float4*)&Ap[(size_t)(m0 + r)*256 + k0 + cq];
            }
            #pragma unroll
            for (int it = 0; it < 2; it++) {
                const int lin = tid + it*256, r = lin >> 3, cq = (lin & 7) * 4;
                pb[it] = *(const float4*)&Bp[(size_t)(brow0 + r)*256 + k0 + cq];
            }
        }

        #pragma unroll
        for (int k8 = 0; k8 < 4; k8++) {
            const uint32_t koff = k8 * 32;
            uint32_t a0[4], a1[4], bA[4], bB[4];
            ldmx4(a0[0], a0[1], a0[2], a0[3], a_addr + koff);
            ldmx4(a1[0], a1[1], a1[2], a1[3], a_addr + 16*AST*4 + koff);
            ldmx4(bA[0], bA[1], bA[2], bA[3], b_addr + koff);
            ldmx4(bB[0], bB[1], bB[2], bB[3], b_addr + 16*AST*4 + koff);
            mma_tf32(acc[0], a0, bA[0], bA[1]);
            mma_tf32(acc[1], a0, bA[2], bA[3]);
            mma_tf32(acc[2], a0, bB[0], bB[1]);
            mma_tf32(acc[3], a0, bB[2], bB[3]);
            mma_tf32(acc[4], a1, bA[0], bA[1]);
            mma_tf32(acc[5], a1, bA[2], bA[3]);
            mma_tf32(acc[6], a1, bB[0], bB[1]);
            mma_tf32(acc[7], a1, bB[2], bB[3]);
        }
        __syncthreads();
    }

    const int rbase = m0 + wm*32 + (lane >> 2);
    const int cbase = n0 + wn*32 + 2*(lane & 3);

    #pragma unroll
    for (int tm = 0; tm < 2; tm++) {
        #pragma unroll
        for (int tn = 0; tn < 4; tn++) {
            const float* ac = acc[tm*4 + tn];
            const int c = cbase + tn*8;
            #pragma unroll
            for (int hrow = 0; hrow < 2; hrow++) {
                const int m = rbase + tm*16 + hrow*8;
                const float v0 = ac[hrow*2], v1 = ac[hrow*2 + 1];
                if (mode == MODE_QKV) {
                    const int b_ = m >> 11, s_ = m & 2047;
                    const int h_ = c / 96, buf = (c >> 5) % 3, d_ = c & 31;
                    const size_t dst = ((size_t)((b_*NHEAD + h_)*SEQ + s_))*HDIM + d_;
                    if (buf == 2) {
                        *(uint32_t*)&vb[dst] = pack_f16x2(v0 + bias[c], v1 + bias[c+1]);
                    } else {
                        const float sc = (buf == 0) ? Q_PRESCALE : 1.0f;
                        const uint32_t pk = pack_bf16x2((v0 + bias[c])*sc,
                                                        (v1 + bias[c+1])*sc);
                        __nv_bfloat16* base = (buf == 0) ? qb : kb;
                        *(uint32_t*)&base[dst] = pk;
                    }
                } else if (mode == MODE_FC) {
                    float2 o;
                    o.x = fmaxf(v0 + bias[c],   0.f);
                    o.y = fmaxf(v1 + bias[c+1], 0.f);
                    *(float2*)&C[(size_t)m*256 + c] = o;
                } else if (mode == MODE_ZR) {
                    if (!half) {
                        float2 o;
                        o.x = 1.f/(1.f + __expf(-(v0 + bias[c])));
                        o.y = 1.f/(1.f + __expf(-(v1 + bias[c+1])));
                        *(float2*)&C[(size_t)m*256 + c] = o;
                    } else {
                        const int nc = c - 256;
                        const float2 xv = *(const float2*)&X[(size_t)m*256 + nc];
                        float2 o;
                        o.x = xv.x / (1.f + __expf(-v0));
                        o.y = xv.y / (1.f + __expf(-v1));
                        *(float2*)&Crx[(size_t)m*256 + nc] = o;
                    }
                } else {
                    const float2 zz = *(const float2*)&Zb[(size_t)m*256 + c];
                    const float2 xv = *(const float2*)&X [(size_t)m*256 + c];
                    float2 o;
                    o.x = (1.f - zz.x)*xv.x + zz.x*tanhf(v0);
                    o.y = (1.f - zz.y)*xv.y + zz.y*tanhf(v1);
                    *(float2*)&C[(size_t)m*256 + c] = o;
                }
            }
        }
    }
}

// ---------------------------------------------------------------------------
// flash attention v4: 32 Q-rows per warp (Q tile 256/CTA) — K/V fragments
// loaded once per warp serve TWO Q row-blocks, halving smem wavefronts
// per MMA. Packed fp16 ex2 softmax, ones-column row sums, fp16 PV.
// ---------------------------------------------------------------------------
__device__ __forceinline__ void mma16816bf(float* d, const uint32_t* a,
                                           uint32_t b0, uint32_t b1)
{
    asm volatile("mma.sync.aligned.m16n8k16.row.col.f32.bf16.bf16.f32 "
                 "{%0,%1,%2,%3},{%4,%5,%6,%7},{%8,%9},{%0,%1,%2,%3};\n"
                 : "+f"(d[0]), "+f"(d[1]), "+f"(d[2]), "+f"(d[3])
                 : "r"(a[0]), "r"(a[1]), "r"(a[2]), "r"(a[3]),
                   "r"(b0), "r"(b1));
}

__device__ __forceinline__ void mma16816h(float* d, const uint32_t* a,
                                          uint32_t b0, uint32_t b1)
{
    asm volatile("mma.sync.aligned.m16n8k16.row.col.f32.f16.f16.f32 "
                 "{%0,%1,%2,%3},{%4,%5,%6,%7},{%8,%9},{%0,%1,%2,%3};\n"
                 : "+f"(d[0]), "+f"(d[1]), "+f"(d[2]), "+f"(d[3])
                 : "r"(a[0]), "r"(a[1]), "r"(a[2]), "r"(a[3]),
                   "r"(b0), "r"(b1));
}

#define KS_STRIDE 36
#define VP_STRIDE 36
#define KS_WORDS  (64*KS_STRIDE)
#define VP_WORDS  (32*VP_STRIDE)

__global__ void __launch_bounds__(256, 1)
attn_mma(const __nv_bfloat16* __restrict__ q,
         const __nv_bfloat16* __restrict__ k,
         const __half* __restrict__ v,
         const uint32_t* __restrict__ mask,
         float* __restrict__ outp)
{
    const int tid  = threadIdx.x;
    const int lane = tid & 31;
    const int w    = tid >> 5;
    const int h    = blockIdx.y;
    const int b    = blockIdx.z;
    const int q0   = blockIdx.x * 256;           // 256-row Q tile

    const size_t nb = (size_t)(b*NHEAD + h) * SEQ;
    const int gr = w*32 + (lane >> 2);           // base q-row; blocks at +16j, halves at +8
    const int c2 = (lane & 3) * 2;

    __shared__ uint32_t Ks[2][KS_WORDS];
    __shared__ uint32_t Vp[2][VP_WORDS];

    // Q fragments: 2 row-blocks x 2 k-chunks
    uint32_t qa[2][2][4];
    {
        const __nv_bfloat16* qbase = q + (nb + q0) * HDIM;
        #pragma unroll
        for (int j = 0; j < 2; j++) {
            #pragma unroll
            for (int kt = 0; kt < 2; kt++) {
                const int r0 = gr + 16*j;
                qa[j][kt][0] = *(const uint32_t*)&qbase[(size_t)(r0    )*HDIM + kt*16 + c2    ];
                qa[j][kt][1] = *(const uint32_t*)&qbase[(size_t)(r0 + 8)*HDIM + kt*16 + c2    ];
                qa[j][kt][2] = *(const uint32_t*)&qbase[(size_t)(r0    )*HDIM + kt*16 + c2 + 8];
                qa[j][kt][3] = *(const uint32_t*)&qbase[(size_t)(r0 + 8)*HDIM + kt*16 + c2 + 8];
            }
        }
    }

    const int kn  = tid >> 2, kc  = tid & 3;
    const int vkp = tid >> 3, vd0 = (tid & 7) * 4;
    const __nv_bfloat16* kgp = k + (nb + kn   )*HDIM + kc*8;
    const __half*        vg0 = v + (nb + 2*vkp    )*HDIM + vd0;
    const __half*        vg1 = v + (nb + 2*vkp + 1)*HDIM + vd0;

    // 4 mask row streams: rows gr, gr+8, gr+16, gr+24
    const uint32_t* mrow0 = mask + ((size_t)b*SEQ + q0 + gr) * (SEQ/32);
    const uint32_t* mrow1 = mrow0 +  8 * (SEQ/32);
    const uint32_t* mrow2 = mrow0 + 16 * (SEQ/32);
    const uint32_t* mrow3 = mrow0 + 24 * (SEQ/32);

    const uint32_t ks_smem = (uint32_t)__cvta_generic_to_shared(&Ks[0][0]);
    const uint32_t vp_smem = (uint32_t)__cvta_generic_to_shared(&Vp[0][0]);
    const uint32_t ks_lane = ks_smem + (((lane & 7)*KS_STRIDE + (lane >> 3)*4) << 2);
    const uint32_t vp_lane = vp_smem + (((lane & 7)*VP_STRIDE + (lane >> 3)*4) << 2);

    const uint32_t ones = ((lane >> 2) == 0) ? 0x3C003C00u : 0u;

    float o[2][4][4];
    #pragma unroll
    for (int j = 0; j < 2; j++)
        #pragma unroll
        for (int i = 0; i < 4; i++)
            #pragma unroll
            for (int t = 0; t < 4; t++) o[j][i][t] = 0.f;
    float o4[2][4] = {{0.f,0.f,0.f,0.f},{0.f,0.f,0.f,0.f}};

    uint4 kv  = *(const uint4*)kgp;
    uint2 vr0 = *(const uint2*)vg0;
    uint2 vr1 = *(const uint2*)vg1;
    uint2 m0w = *(const uint2*)&mrow0[0];
    uint2 m1w = *(const uint2*)&mrow1[0];
    uint2 m2w = *(const uint2*)&mrow2[0];
    uint2 m3w = *(const uint2*)&mrow3[0];

    for (int kt = 0; kt < SEQ/64; kt++) {
        const int buf = kt & 1;

        *(uint4*)&Ks[buf][kn*KS_STRIDE + kc*4] = kv;
        Vp[buf][(vd0    )*VP_STRIDE + vkp] = __byte_perm(vr0.x, vr1.x, 0x5410);
        Vp[buf][(vd0 + 1)*VP_STRIDE + vkp] = __byte_perm(vr0.x, vr1.x, 0x7632);
        Vp[buf][(vd0 + 2)*VP_STRIDE + vkp] = __byte_perm(vr0.y, vr1.y, 0x5410);
        Vp[buf][(vd0 + 3)*VP_STRIDE + vkp] = __byte_perm(vr0.y, vr1.y, 0x7632);
        const uint2 cm0 = m0w, cm1 = m1w, cm2 = m2w, cm3 = m3w;
        __syncthreads();

        if (kt + 1 < SEQ/64) {
            const int koff = (kt + 1) * 64 * HDIM;
            kv  = *(const uint4*)(kgp + koff);
            vr0 = *(const uint2*)(vg0 + koff);
            vr1 = *(const uint2*)(vg1 + koff);
            m0w = *(const uint2*)&mrow0[(kt + 1)*2];
            m1w = *(const uint2*)&mrow1[(kt + 1)*2];
            m2w = *(const uint2*)&mrow2[(kt + 1)*2];
            m3w = *(const uint2*)&mrow3[(kt + 1)*2];
        }

        // ---- scores + packed exp + mask (both row-blocks per K fragment) ----
        const uint32_t ksb = ks_lane + buf*(KS_WORDS*4);
        uint32_t P0[2][8], P1[2][8];
        #pragma unroll
        for (int nt = 0; nt < 8; nt++) {
            uint32_t kb0, kb1, kb2, kb3;
            ldmx4(kb0, kb1, kb2, kb3, ksb + nt*(8*KS_STRIDE*4));
            const int sh = ((nt & 3) * 8) + c2;
            // block 0 (rows gr, gr+8)
            {
                float s[4] = {0.f, 0.f, 0.f, 0.f};
                mma16816bf(s, qa[0][0], kb0, kb1);
                mma16816bf(s, qa[0][1], kb2, kb3);
                const uint32_t ulo = ((nt < 4) ? cm0.x : cm0.y) >> sh;
                const uint32_t uhi = ((nt < 4) ? cm1.x : cm1.y) >> sh;
                const uint32_t mwlo = (ulo & 1u)*0xFFFFu + (ulo & 2u)*0x7FFF8000u;
                const uint32_t mwhi = (uhi & 1u)*0xFFFFu + (uhi & 2u)*0x7FFF8000u;
                P0[0][nt] = ex2_f16x2(pack_f16x2(s[0], s[1])) & mwlo;
                P1[0][nt] = ex2_f16x2(pack_f16x2(s[2], s[3])) & mwhi;
            }
            // block 1 (rows gr+16, gr+24)
            {
                float s[4] = {0.f, 0.f, 0.f, 0.f};
                mma16816bf(s, qa[1][0], kb0, kb1);
                mma16816bf(s, qa[1][1], kb2, kb3);
                const uint32_t ulo = ((nt < 4) ? cm2.x : cm2.y) >> sh;
                const uint32_t uhi = ((nt < 4) ? cm3.x : cm3.y) >> sh;
                const uint32_t mwlo = (ulo & 1u)*0xFFFFu + (ulo & 2u)*0x7FFF8000u;
                const uint32_t mwhi = (uhi & 1u)*0xFFFFu + (uhi & 2u)*0x7FFF8000u;
                P0[1][nt] = ex2_f16x2(pack_f16x2(s[0], s[1])) & mwlo;
                P1[1][nt] = ex2_f16x2(pack_f16x2(s[2], s[3])) & mwhi;
            }
        }

        // ---- PV + ones-column row sums (V fragments shared across blocks) ----
        const uint32_t vpb = vp_lane + buf*(VP_WORDS*4);
        #pragma unroll
        for (int hf = 0; hf < 2; hf++) {
            uint32_t aA[2][4], aB[2][4];
            #pragma unroll
            for (int j = 0; j < 2; j++) {
                aA[j][0] = P0[j][4*hf    ]; aA[j][1] = P1[j][4*hf    ];
                aA[j][2] = P0[j][4*hf + 1]; aA[j][3] = P1[j][4*hf + 1];
                aB[j][0] = P0[j][4*hf + 2]; aB[j][1] = P1[j][4*hf + 2];
                aB[j][2] = P0[j][4*hf + 3]; aB[j][3] = P1[j][4*hf + 3];
                mma16816h(o4[j], aA[j], ones, ones);
                mma16816h(o4[j], aB[j], ones, ones);
            }
            #pragma unroll
            for (int dt = 0; dt < 4; dt++) {
                uint32_t vb0, vb1, vb2, vb3;
                ldmx4(vb0, vb1, vb2, vb3, vpb + dt*(8*VP_STRIDE*4) + hf*64);
                #pragma unroll
                for (int j = 0; j < 2; j++) {
                    mma16816h(o[j][dt], aA[j], vb0, vb1);
                    mma16816h(o[j][dt], aB[j], vb2, vb3);
                }
            }
        }
    }

    const int n_  = b*NHEAD + h;
    const int bo  = n_ & 3;
    const int hp  = n_ >> 2;
    #pragma unroll
    for (int j = 0; j < 2; j++) {
        const float sum_lo = __shfl_sync(0xffffffffu, o4[j][0], lane & ~3);
        const float sum_hi = __shfl_sync(0xffffffffu, o4[j][2], lane & ~3);
        const float inv_lo = 1.f / sum_lo;
        const float inv_hi = 1.f / sum_hi;
        #pragma unroll
        for (int dt = 0; dt < 4; dt++) {
            const size_t base = ((size_t)(bo*SEQ + q0 + gr + 16*j))*DIM
                                + hp*HDIM + dt*8 + c2;
            float2 lo, hi;
            lo.x = o[j][dt][0]*inv_lo; lo.y = o[j][dt][1]*inv_lo;
            hi.x = o[j][dt][2]*inv_hi; hi.y = o[j][dt][3]*inv_hi;
            *(float2*)&outp[base]         = lo;
            *(float2*)&outp[base + 8*DIM] = hi;
        }
    }
}

// ---------------------------------------------------------------------------
extern "C" void kernel_launch(void* const* d_in, const int* in_sizes, int n_in,
                              void* d_out, int out_size)
{
    const float* x     = (const float*)d_in[0];
    const int*   adj   = (const int*)  d_in[1];
    const float* w_qkv = (const float*)d_in[2];
    const float* b_qkv = (const float*)d_in[3];
    const float* ln_g  = (const float*)d_in[4];
    const float* ln_b  = (const float*)d_in[5];
    const float* w_fc  = (const float*)d_in[6];
    const float* b_fc  = (const float*)d_in[7];
    const float* w_z   = (const float*)d_in[8];
    const float* b_z   = (const float*)d_in[9];
    const float* u_z   = (const float*)d_in[10];
    const float* w_r   = (const float*)d_in[11];
    const float* u_r   = (const float*)d_in[12];
    const float* w_g   = (const float*)d_in[13];
    const float* u_g   = (const float*)d_in[14];
    float* out = (float*)d_out;

    float *xn, *att, *y, *z, *rx;
    __nv_bfloat16 *qb, *kb;
    __half *vb;
    uint32_t *mask;
    cudaGetSymbolAddress((void**)&xn,   g_xn);
    cudaGetSymbolAddress((void**)&att,  g_att);
    cudaGetSymbolAddress((void**)&y,    g_y);
    cudaGetSymbolAddress((void**)&z,    g_z);
    cudaGetSymbolAddress((void**)&rx,   g_rx);
    cudaGetSymbolAddress((void**)&qb,   g_q);
    cudaGetSymbolAddress((void**)&kb,   g_k);
    cudaGetSymbolAddress((void**)&vb,   g_v);
    cudaGetSymbolAddress((void**)&mask, g_mask);

    // 0. pack adjacency into bitmask
    pack_adj<<<BATCH*SEQ*SEQ/256, 256>>>(adj, mask);
    // 1. LayerNorm
    ln_kernel<<<M_TOT, 256>>>(x, ln_g, ln_b, xn);
    // 2. QKV projection (tf32 TC) -> q (bf16, log2-prescaled), k (bf16), v (fp16)
    gemm_tc<<<dim3(12, 64), 256>>>(xn, nullptr, w_qkv, nullptr, nullptr, nullptr,
                                   b_qkv, nullptr, nullptr,
                                   nullptr, nullptr, qb, kb, vb, MODE_QKV, 8);
    // 3. flash attention (Q tile 256, 32 rows/warp)
    attn_mma<<<dim3(SEQ/256, NHEAD, BATCH), 256>>>(qb, kb, vb, mask, att);
    // 4. FC + ReLU
    gemm_tc<<<dim3(4, 64), 256>>>(att, nullptr, w_fc, nullptr, nullptr, nullptr,
                                  b_fc, nullptr, nullptr,
                                  y, nullptr, nullptr, nullptr, nullptr, MODE_FC, 8);
    // 5. fused ZR: z = sigmoid(y@w_z^T+b_z+x@u_z^T); rx = sigmoid(y@w_r^T+x@u_r^T)*x
    gemm_tc<<<dim3(8, 64), 256>>>(y, x, w_z, u_z, w_r, u_r,
                                  b_z, x, nullptr,
                                  z, rx, nullptr, nullptr, nullptr, MODE_ZR, 16);
    // 6. H: out = (1-z)*x + z*tanh(y@w_g^T + rx@u_g^T)
    gemm_tc<<<dim3(4, 64), 256>>>(y, rx, w_g, u_g, nullptr, nullptr,
                                  nullptr, x, z,
                                  out, nullptr, nullptr, nullptr, nullptr, MODE_H, 16);
}